// round 2
// baseline (speedup 1.0000x reference)
#include <cuda_runtime.h>

#define BATCH 4096
#define NE    64
#define EPSV  1e-5f

// ---------------- scratch (device globals; no runtime allocation) ----------
__device__ float g_buf0[BATCH * 256];
__device__ float g_buf1[BATCH * 256];
__device__ float g_buf2[BATCH * 256];
__device__ float g_w  [BATCH * NE];
__device__ float g_wn [BATCH * NE];

// ---------------- small GEMM: C[M,N] = X[M,K] @ W[N,K]^T + bias[N] ---------
// M=4096, K%16==0, N%64==0. 64x64x16 tile, 4x4 microtile, 256 threads.
__global__ __launch_bounds__(256)
void gemm_bias_kernel(const float* __restrict__ X, const float* __restrict__ W,
                      const float* __restrict__ bias, float* __restrict__ C,
                      int K, int N) {
    const int BM = 64, BN = 64, BK = 16, TM = 4, TN = 4;
    __shared__ __align__(16) float As[BK][BM];
    __shared__ __align__(16) float Bs[BK][BN];
    int tid  = threadIdx.x;
    int n0   = blockIdx.x * BN;
    int m0   = blockIdx.y * BM;
    int tn   = tid & 15, tm = tid >> 4;
    int row0 = tm * TM, col0 = tn * TN;
    int lr   = tid >> 2, ls = tid & 3;   // 64 rows x 4 float4 segs = 256 loads
    float acc[TM][TN] = {};
    for (int k0 = 0; k0 < K; k0 += BK) {
        float4 av = *reinterpret_cast<const float4*>(&X[(size_t)(m0 + lr) * K + k0 + ls * 4]);
        As[ls*4+0][lr] = av.x; As[ls*4+1][lr] = av.y; As[ls*4+2][lr] = av.z; As[ls*4+3][lr] = av.w;
        float4 bv = *reinterpret_cast<const float4*>(&W[(size_t)(n0 + lr) * K + k0 + ls * 4]);
        Bs[ls*4+0][lr] = bv.x; Bs[ls*4+1][lr] = bv.y; Bs[ls*4+2][lr] = bv.z; Bs[ls*4+3][lr] = bv.w;
        __syncthreads();
        #pragma unroll
        for (int kk = 0; kk < BK; ++kk) {
            float a[TM], b[TN];
            float4 va = *reinterpret_cast<const float4*>(&As[kk][row0]);
            a[0]=va.x; a[1]=va.y; a[2]=va.z; a[3]=va.w;
            float4 vb = *reinterpret_cast<const float4*>(&Bs[kk][col0]);
            b[0]=vb.x; b[1]=vb.y; b[2]=vb.z; b[3]=vb.w;
            #pragma unroll
            for (int i = 0; i < TM; i++)
                #pragma unroll
                for (int j = 0; j < TN; j++)
                    acc[i][j] = fmaf(a[i], b[j], acc[i][j]);
        }
        __syncthreads();
    }
    #pragma unroll
    for (int i = 0; i < TM; i++)
        #pragma unroll
        for (int j = 0; j < TN; j++)
            C[(size_t)(m0 + row0 + i) * N + n0 + col0 + j] = acc[i][j] + bias[n0 + col0 + j];
}

// ------------- fused BatchNorm (training stats, biased var) + PReLU --------
// In-place on X[4096, C]. One block handles 32 columns, all 4096 rows, 2 passes.
__global__ __launch_bounds__(1024)
void bn_prelu_kernel(float* __restrict__ X, const float* __restrict__ g,
                     const float* __restrict__ be, const float* __restrict__ aP,
                     int C) {
    __shared__ float s1[32][33];
    __shared__ float s2[32][33];
    int tx = threadIdx.x, ty = threadIdx.y;
    int col = blockIdx.x * 32 + tx;
    float sum = 0.f, sq = 0.f;
    for (int r = ty; r < BATCH; r += 32) {
        float v = X[(size_t)r * C + col];
        sum += v; sq += v * v;
    }
    s1[ty][tx] = sum; s2[ty][tx] = sq;
    __syncthreads();
    for (int off = 16; off > 0; off >>= 1) {
        if (ty < off) { s1[ty][tx] += s1[ty+off][tx]; s2[ty][tx] += s2[ty+off][tx]; }
        __syncthreads();
    }
    float mean = s1[0][tx] * (1.f / BATCH);
    float var  = s2[0][tx] * (1.f / BATCH) - mean * mean;
    float sc   = g[col] * rsqrtf(var + EPSV);
    float sh   = be[col] - mean * sc;
    float a    = aP[0];
    for (int r = ty; r < BATCH; r += 32) {
        float v = X[(size_t)r * C + col] * sc + sh;
        X[(size_t)r * C + col] = (v >= 0.f) ? v : a * v;
    }
}

// -------- w_sum = sum(all of w); wn = w / w_sum (single-block, 2 passes) ---
__global__ __launch_bounds__(1024)
void wsum_scale_kernel(const float* __restrict__ w, float* __restrict__ wn) {
    const int n = BATCH * NE;
    __shared__ float sm[1024];
    int tid = threadIdx.x;
    float s = 0.f;
    for (int i = tid; i < n; i += 1024) s += w[i];
    sm[tid] = s; __syncthreads();
    for (int off = 512; off > 0; off >>= 1) {
        if (tid < off) sm[tid] += sm[tid + off];
        __syncthreads();
    }
    float inv = 1.f / sm[0];
    for (int i = tid; i < n; i += 1024) wn[i] = w[i] * inv;
}

// -------- out[b,o] = sum_e wn[b,e] * bias[e,o]  (accumulator init) ---------
__global__ __launch_bounds__(256)
void bias_combine_kernel(const float* __restrict__ wn, const float* __restrict__ bias,
                         float* __restrict__ out, int O) {
    int idx = blockIdx.x * 256 + threadIdx.x;
    int b = idx / O, o = idx - b * O;
    const float* wr = wn + (size_t)b * NE;
    float acc = 0.f;
    #pragma unroll 8
    for (int e = 0; e < NE; e++) acc = fmaf(wr[e], bias[(size_t)e * O + o], acc);
    out[idx] = acc;
}

// -------- expert combine GEMM: out[b,o] += sum_e wn[b,e]*(z[b,:].W[e,o,:]) -
// A-tile generated in SMEM as wn[b,e]*z[b,k]; K-loop = (expert, k). Split-K
// over experts via gridDim.z; fp32 atomicAdd into bias-initialized out.
// BM=128 fixed; BN/TN templated (128/8 for O=256, 64/4 for O=64). 256 thr.
template<int BN, int TN>
__global__ __launch_bounds__(256)
void expert_gemm_kernel(const float* __restrict__ Z, const float* __restrict__ W,
                        const float* __restrict__ wn, float* __restrict__ out,
                        int I, int O, int eper) {
    const int BM = 128, TM = 8, BK = 8;
    __shared__ __align__(16) float As[BK][BM];
    __shared__ __align__(16) float Bs[BK][BN];
    __shared__ float wns[BM];
    int tid = threadIdx.x;
    int n0  = blockIdx.x * BN;
    int m0  = blockIdx.y * BM;
    int e0  = blockIdx.z * eper;
    const int NT = BN / TN;
    int tn  = tid % NT, tm = tid / NT;
    int row0 = tm * TM, col0 = tn * TN;
    int ar = tid >> 1, aseg = tid & 1;   // 128 rows x 2 float4 segs = 256
    float acc[TM][TN] = {};
    for (int e = e0; e < e0 + eper; ++e) {
        if (tid < BM) wns[tid] = wn[(size_t)(m0 + tid) * NE + e];
        __syncthreads();
        const float* We = W + (size_t)e * O * I;
        for (int k0 = 0; k0 < I; k0 += BK) {
            float4 av = *reinterpret_cast<const float4*>(&Z[(size_t)(m0 + ar) * I + k0 + aseg * 4]);
            float s = wns[ar];
            As[aseg*4+0][ar] = av.x * s; As[aseg*4+1][ar] = av.y * s;
            As[aseg*4+2][ar] = av.z * s; As[aseg*4+3][ar] = av.w * s;
            if (BN == 128) {
                float4 bv = *reinterpret_cast<const float4*>(&We[(size_t)(n0 + ar) * I + k0 + aseg * 4]);
                Bs[aseg*4+0][ar] = bv.x; Bs[aseg*4+1][ar] = bv.y;
                Bs[aseg*4+2][ar] = bv.z; Bs[aseg*4+3][ar] = bv.w;
            } else {
                if (tid < 2 * BN) {
                    int br = tid >> 1, bs = tid & 1;
                    float4 bv = *reinterpret_cast<const float4*>(&We[(size_t)(n0 + br) * I + k0 + bs * 4]);
                    Bs[bs*4+0][br] = bv.x; Bs[bs*4+1][br] = bv.y;
                    Bs[bs*4+2][br] = bv.z; Bs[bs*4+3][br] = bv.w;
                }
            }
            __syncthreads();
            #pragma unroll
            for (int kk = 0; kk < BK; ++kk) {
                float a[TM], b[TN];
                #pragma unroll
                for (int i = 0; i < TM; i += 4) {
                    float4 v = *reinterpret_cast<const float4*>(&As[kk][row0 + i]);
                    a[i]=v.x; a[i+1]=v.y; a[i+2]=v.z; a[i+3]=v.w;
                }
                #pragma unroll
                for (int j = 0; j < TN; j += 4) {
                    float4 v = *reinterpret_cast<const float4*>(&Bs[kk][col0 + j]);
                    b[j]=v.x; b[j+1]=v.y; b[j+2]=v.z; b[j+3]=v.w;
                }
                #pragma unroll
                for (int i = 0; i < TM; i++)
                    #pragma unroll
                    for (int j = 0; j < TN; j++)
                        acc[i][j] = fmaf(a[i], b[j], acc[i][j]);
            }
            __syncthreads();
        }
    }
    #pragma unroll
    for (int i = 0; i < TM; i++)
        #pragma unroll
        for (int j = 0; j < TN; j++)
            atomicAdd(&out[(size_t)(m0 + row0 + i) * O + n0 + col0 + j], acc[i][j]);
}

// ---------------------------------------------------------------------------
extern "C" void kernel_launch(void* const* d_in, const int* in_sizes, int n_in,
                              void* d_out, int out_size) {
    const float* m0    = (const float*)d_in[0];
    const float* x0    = (const float*)d_in[1];
    const float* mW1   = (const float*)d_in[2];
    const float* mb1   = (const float*)d_in[3];
    const float* mg1   = (const float*)d_in[4];
    const float* mbe1  = (const float*)d_in[5];
    const float* ma1   = (const float*)d_in[6];
    const float* mW2   = (const float*)d_in[7];
    const float* mb2   = (const float*)d_in[8];
    const float* mg2   = (const float*)d_in[9];
    const float* mbe2  = (const float*)d_in[10];
    const float* ma2   = (const float*)d_in[11];
    const float* mW3   = (const float*)d_in[12];
    const float* mb3   = (const float*)d_in[13];
    const float* mg3   = (const float*)d_in[14];
    const float* mbe3  = (const float*)d_in[15];
    const float* ma3   = (const float*)d_in[16];
    const float* Wenc0 = (const float*)d_in[17];
    const float* benc0 = (const float*)d_in[18];
    const float* Wenc1 = (const float*)d_in[19];
    const float* benc1 = (const float*)d_in[20];
    const float* Wdec0 = (const float*)d_in[21];
    const float* bdec0 = (const float*)d_in[22];
    const float* Wdec1 = (const float*)d_in[23];
    const float* bdec1 = (const float*)d_in[24];
    const float* bng   = (const float*)d_in[25];
    const float* bnb   = (const float*)d_in[26];
    const float* aP    = (const float*)d_in[27];
    float* out = (float*)d_out;

    float *b0, *b1, *b2, *w, *wn;
    cudaGetSymbolAddress((void**)&b0, g_buf0);
    cudaGetSymbolAddress((void**)&b1, g_buf1);
    cudaGetSymbolAddress((void**)&b2, g_buf2);
    cudaGetSymbolAddress((void**)&w,  g_w);
    cudaGetSymbolAddress((void**)&wn, g_wn);

    dim3 blkBN(32, 32);

    // ---- MNet: 3x (Linear -> BN -> PReLU) -> w [4096,64] ----
    gemm_bias_kernel<<<dim3(4, 64), 256>>>(m0, mW1, mb1, b0, 128, 256);
    bn_prelu_kernel<<<8, blkBN>>>(b0, mg1, mbe1, ma1, 256);
    gemm_bias_kernel<<<dim3(2, 64), 256>>>(b0, mW2, mb2, b1, 256, 128);
    bn_prelu_kernel<<<4, blkBN>>>(b1, mg2, mbe2, ma2, 128);
    gemm_bias_kernel<<<dim3(1, 64), 256>>>(b1, mW3, mb3, w, 128, 64);
    bn_prelu_kernel<<<2, blkBN>>>(w, mg3, mbe3, ma3, 64);
    wsum_scale_kernel<<<1, 1024>>>(w, wn);

    // ---- encoder layer 0: x0[4096,64] -> b2[4096,256] ----
    bias_combine_kernel<<<BATCH * 256 / 256, 256>>>(wn, benc0, b2, 256);
    expert_gemm_kernel<128, 8><<<dim3(2, 32, 4), 256>>>(x0, Wenc0, wn, b2, 64, 256, 16);
    bn_prelu_kernel<<<8, blkBN>>>(b2, bng, bnb, aP, 256);

    // ---- encoder layer 1: b2 -> b0 ----
    bias_combine_kernel<<<BATCH * 256 / 256, 256>>>(wn, benc1, b0, 256);
    expert_gemm_kernel<128, 8><<<dim3(2, 32, 8), 256>>>(b2, Wenc1, wn, b0, 256, 256, 8);
    bn_prelu_kernel<<<8, blkBN>>>(b0, bng, bnb, aP, 256);

    // ---- decoder layer 0: b0 -> b1 ----
    bias_combine_kernel<<<BATCH * 256 / 256, 256>>>(wn, bdec0, b1, 256);
    expert_gemm_kernel<128, 8><<<dim3(2, 32, 8), 256>>>(b0, Wdec0, wn, b1, 256, 256, 8);
    bn_prelu_kernel<<<8, blkBN>>>(b1, bng, bnb, aP, 256);

    // ---- decoder layer 1 (no BN/PReLU): b1 -> out [4096,64] ----
    bias_combine_kernel<<<BATCH * 64 / 256, 256>>>(wn, bdec1, out, 64);
    expert_gemm_kernel<64, 4><<<dim3(1, 32, 8), 256>>>(b1, Wdec1, wn, out, 256, 64, 8);
}

// round 4
// speedup vs baseline: 2.0268x; 2.0268x over previous
#include <cuda_runtime.h>
#include <cuda_bf16.h>
#include <cstdint>

#define BATCH 4096
#define NE    64
#define EPSV  1e-5f

// ===================== device scratch (no runtime alloc) ====================
__device__ __align__(16) float g_buf0[BATCH * 256];
__device__ __align__(16) float g_buf1[BATCH * 256];
__device__ __align__(16) float g_buf2[BATCH * 256];
__device__ __align__(16) float g_w   [BATCH * NE];
__device__ float g_sum, g_inv;

// split-bf16 weights: enc0(1M) enc1(4M) dec0(4M) dec1(1M) = 10.5M elems
#define OFF_ENC0 0
#define OFF_ENC1 1048576
#define OFF_DEC0 5242880
#define OFF_DEC1 9437184
#define W_TOTAL  10485760
__device__ __align__(16) __nv_bfloat16 g_Wh[W_TOTAL];
__device__ __align__(16) __nv_bfloat16 g_Wl[W_TOTAL];

// ===================== PTX helpers (base sm_103 target only) ===============
__device__ __forceinline__ uint32_t smem_u32(const void* p) {
    uint32_t a;
    asm("{ .reg .u64 t; cvta.to.shared.u64 t, %1; cvt.u32.u64 %0, t; }"
        : "=r"(a) : "l"(p));
    return a;
}

#define LDSM4(r, a) \
    asm volatile("ldmatrix.sync.aligned.m8n8.x4.shared.b16 {%0,%1,%2,%3}, [%4];" \
        : "=r"((r)[0]), "=r"((r)[1]), "=r"((r)[2]), "=r"((r)[3]) : "r"(a))

#define MMA16816(d, a, b0v, b1v) \
    asm volatile("mma.sync.aligned.m16n8k16.row.col.f32.bf16.bf16.f32 " \
        "{%0,%1,%2,%3}, {%4,%5,%6,%7}, {%8,%9}, {%0,%1,%2,%3};" \
        : "+f"((d)[0]), "+f"((d)[1]), "+f"((d)[2]), "+f"((d)[3]) \
        : "r"((a)[0]), "r"((a)[1]), "r"((a)[2]), "r"((a)[3]), "r"(b0v), "r"(b1v))

#define CP_ASYNC16(dst, src) \
    asm volatile("cp.async.cg.shared.global [%0], [%1], 16;" :: "r"(dst), "l"(src))
#define CP_COMMIT() asm volatile("cp.async.commit_group;" ::: "memory")
#define CP_WAIT1()  asm volatile("cp.async.wait_group 1;" ::: "memory")
#define CP_WAIT0()  asm volatile("cp.async.wait_group 0;" ::: "memory")

// ===================== weight pre-split fp32 -> bf16 hi/lo =================
__global__ __launch_bounds__(256)
void split_w_kernel(const float* __restrict__ W, __nv_bfloat16* __restrict__ Wh,
                    __nv_bfloat16* __restrict__ Wl, int n4) {
    int i = blockIdx.x * 256 + threadIdx.x;
    if (i >= n4) return;
    float4 v = reinterpret_cast<const float4*>(W)[i];
    float f[4] = {v.x, v.y, v.z, v.w};
    __nv_bfloat16 h[4], l[4];
    #pragma unroll
    for (int j = 0; j < 4; ++j) {
        h[j] = __float2bfloat16_rn(f[j]);
        l[j] = __float2bfloat16_rn(f[j] - __bfloat162float(h[j]));
    }
    ushort4 hv = make_ushort4(*(unsigned short*)&h[0], *(unsigned short*)&h[1],
                              *(unsigned short*)&h[2], *(unsigned short*)&h[3]);
    ushort4 lv = make_ushort4(*(unsigned short*)&l[0], *(unsigned short*)&l[1],
                              *(unsigned short*)&l[2], *(unsigned short*)&l[3]);
    reinterpret_cast<ushort4*>(Wh)[i] = hv;
    reinterpret_cast<ushort4*>(Wl)[i] = lv;
}

// ===================== small GEMM (MNet, fp32 SIMT) ========================
__global__ __launch_bounds__(256)
void gemm_bias_kernel(const float* __restrict__ X, const float* __restrict__ W,
                      const float* __restrict__ bias, float* __restrict__ C,
                      int K, int N) {
    const int BM = 64, BN = 64, BK = 16, TM = 4, TN = 4;
    __shared__ __align__(16) float As[BK][BM];
    __shared__ __align__(16) float Bs[BK][BN];
    int tid  = threadIdx.x;
    int n0   = blockIdx.x * BN;
    int m0   = blockIdx.y * BM;
    int tn   = tid & 15, tm = tid >> 4;
    int row0 = tm * TM, col0 = tn * TN;
    int lr   = tid >> 2, ls = tid & 3;
    float acc[TM][TN] = {};
    for (int k0 = 0; k0 < K; k0 += BK) {
        float4 av = *reinterpret_cast<const float4*>(&X[(size_t)(m0 + lr) * K + k0 + ls * 4]);
        As[ls*4+0][lr] = av.x; As[ls*4+1][lr] = av.y; As[ls*4+2][lr] = av.z; As[ls*4+3][lr] = av.w;
        float4 bv = *reinterpret_cast<const float4*>(&W[(size_t)(n0 + lr) * K + k0 + ls * 4]);
        Bs[ls*4+0][lr] = bv.x; Bs[ls*4+1][lr] = bv.y; Bs[ls*4+2][lr] = bv.z; Bs[ls*4+3][lr] = bv.w;
        __syncthreads();
        #pragma unroll
        for (int kk = 0; kk < BK; ++kk) {
            float a[TM], b[TN];
            float4 va = *reinterpret_cast<const float4*>(&As[kk][row0]);
            a[0]=va.x; a[1]=va.y; a[2]=va.z; a[3]=va.w;
            float4 vb = *reinterpret_cast<const float4*>(&Bs[kk][col0]);
            b[0]=vb.x; b[1]=vb.y; b[2]=vb.z; b[3]=vb.w;
            #pragma unroll
            for (int i = 0; i < TM; i++)
                #pragma unroll
                for (int j = 0; j < TN; j++)
                    acc[i][j] = fmaf(a[i], b[j], acc[i][j]);
        }
        __syncthreads();
    }
    #pragma unroll
    for (int i = 0; i < TM; i++)
        #pragma unroll
        for (int j = 0; j < TN; j++)
            C[(size_t)(m0 + row0 + i) * N + n0 + col0 + j] = acc[i][j] + bias[n0 + col0 + j];
}

// ===================== BN + PReLU, 2 columns per CTA =======================
__global__ __launch_bounds__(256)
void bn_prelu_kernel(float* __restrict__ X, const float* __restrict__ g,
                     const float* __restrict__ be, const float* __restrict__ aP,
                     int C) {
    __shared__ float s1[256], s2[256];
    int tid = threadIdx.x;
    int col = blockIdx.x * 2 + (tid & 1);
    int r0  = tid >> 1;
    float sum = 0.f, sq = 0.f;
    for (int r = r0; r < BATCH; r += 128) {
        float v = X[(size_t)r * C + col];
        sum += v; sq += v * v;
    }
    s1[tid] = sum; s2[tid] = sq;
    __syncthreads();
    #pragma unroll
    for (int off = 128; off >= 2; off >>= 1) {
        if (tid < off) { s1[tid] += s1[tid + off]; s2[tid] += s2[tid + off]; }
        __syncthreads();
    }
    float mean = s1[tid & 1] * (1.f / BATCH);
    float var  = s2[tid & 1] * (1.f / BATCH) - mean * mean;
    float sc   = g[col] * rsqrtf(var + EPSV);
    float sh   = be[col] - mean * sc;
    float a    = aP[0];
    for (int r = r0; r < BATCH; r += 128) {
        float v = X[(size_t)r * C + col] * sc + sh;
        X[(size_t)r * C + col] = (v >= 0.f) ? v : a * v;
    }
}

// ===================== global sum -> inverse ================================
__global__ void zero_sum_kernel() { g_sum = 0.f; }

__global__ __launch_bounds__(256)
void reduce_w_kernel(const float* __restrict__ w) {
    __shared__ float s[256];
    int tid = threadIdx.x;
    float a = 0.f;
    for (int i = blockIdx.x * 256 + tid; i < BATCH * NE; i += gridDim.x * 256) a += w[i];
    s[tid] = a; __syncthreads();
    #pragma unroll
    for (int off = 128; off; off >>= 1) {
        if (tid < off) s[tid] += s[tid + off];
        __syncthreads();
    }
    if (tid == 0) atomicAdd(&g_sum, s[0]);
}

__global__ void inv_kernel() { g_inv = 1.f / g_sum; }

// ============ out[b,o] = inv * sum_e w[b,e]*bias[e,o] (acc init) ===========
__global__ __launch_bounds__(256)
void bias_combine_kernel(const float* __restrict__ w, const float* __restrict__ bias,
                         float* __restrict__ out, int O) {
    int idx = blockIdx.x * 256 + threadIdx.x;
    int b = idx / O, o = idx - b * O;
    float inv = g_inv;
    const float* wr = w + (size_t)b * NE;
    float acc = 0.f;
    #pragma unroll 8
    for (int e = 0; e < NE; e++) acc = fmaf(wr[e], bias[(size_t)e * O + o], acc);
    out[idx] = acc * inv;
}

// ===================== mma.sync expert GEMM (split-bf16) ===================
// out[b,o] += sum_{e,i} (w[b,e]*inv) * z[b,i] * W[e,o,i]
// BM=128, BN=64, BK=32. 8 warps (4M x 2N), warp tile 32x32.
// A generated + hi/lo split in SMEM; B = pre-split Wh/Wl via cp.async.
// Double-buffered; split-K over experts; fp32 atomicAdd epilogue.
// SMEM stage: AH[128x80B] AL BH[64x80B] BL = 30720B; 2 stages = 61440B.
template<int IDIM>
__global__ __launch_bounds__(256, 2)
void expert_mma_kernel(const float* __restrict__ Z,
                       const __nv_bfloat16* __restrict__ Wh,
                       const __nv_bfloat16* __restrict__ Wl,
                       const float* __restrict__ w,
                       float* __restrict__ out,
                       int O, int eper) {
    constexpr int RS    = 80;                 // padded row stride (bytes)
    constexpr int AHo   = 0;
    constexpr int ALo   = 128 * RS;           // 10240
    constexpr int BHo   = 2 * 128 * RS;       // 20480
    constexpr int BSZ   = 64 * RS;            // 5120
    constexpr int STAGE = BHo + 2 * BSZ;      // 30720
    constexpr int CPE   = IDIM / 32;          // chunks per expert

    extern __shared__ char smem[];
    uint32_t sb = smem_u32(smem);

    int tid  = threadIdx.x;
    int lane = tid & 31, wid = tid >> 5;
    int wy = wid >> 1, wx = wid & 1;          // 4 M-warps x 2 N-warps
    int m0 = blockIdx.y * 128;
    int n0 = blockIdx.x * 64;
    int e0 = blockIdx.z * eper;
    float inv = g_inv;

    const int nc = eper * CPE;

    // per-thread A-gen constants
    int ar  = tid >> 1;                       // row 0..127
    int asg = tid & 1;                        // k-half seg (16 floats)
    const float* zrow = Z + (size_t)(m0 + ar) * IDIM + asg * 16;
    const float* wrow = w + (size_t)(m0 + ar) * NE;

    auto load_chunk = [&](int c, int buf) {
        int e  = e0 + c / CPE;
        int i0 = (c % CPE) * 32;
        // ---- A: p = w*inv*z -> bf16 hi/lo, STS ----
        {
            float sc = wrow[e] * inv;
            const float* zr = zrow + i0;
            float4 v0 = *reinterpret_cast<const float4*>(zr);
            float4 v1 = *reinterpret_cast<const float4*>(zr + 4);
            float4 v2 = *reinterpret_cast<const float4*>(zr + 8);
            float4 v3 = *reinterpret_cast<const float4*>(zr + 12);
            float f[16] = {v0.x,v0.y,v0.z,v0.w, v1.x,v1.y,v1.z,v1.w,
                           v2.x,v2.y,v2.z,v2.w, v3.x,v3.y,v3.z,v3.w};
            uint32_t hw[8], lw[8];
            #pragma unroll
            for (int j = 0; j < 8; ++j) {
                float p0 = f[2*j] * sc, p1 = f[2*j+1] * sc;
                __nv_bfloat162 h2 = __floats2bfloat162_rn(p0, p1);
                float q0 = p0 - __low2float(h2);
                float q1 = p1 - __high2float(h2);
                __nv_bfloat162 l2 = __floats2bfloat162_rn(q0, q1);
                hw[j] = *reinterpret_cast<uint32_t*>(&h2);
                lw[j] = *reinterpret_cast<uint32_t*>(&l2);
            }
            char* basep = smem + buf * STAGE;
            int so = ar * RS + asg * 32;
            *reinterpret_cast<uint4*>(basep + AHo + so)      = make_uint4(hw[0],hw[1],hw[2],hw[3]);
            *reinterpret_cast<uint4*>(basep + AHo + so + 16) = make_uint4(hw[4],hw[5],hw[6],hw[7]);
            *reinterpret_cast<uint4*>(basep + ALo + so)      = make_uint4(lw[0],lw[1],lw[2],lw[3]);
            *reinterpret_cast<uint4*>(basep + ALo + so + 16) = make_uint4(lw[4],lw[5],lw[6],lw[7]);
        }
        // ---- B: cp.async 64 rows x 32 k, hi+lo ----
        {
            uint32_t dbase = sb + buf * STAGE + BHo;
            #pragma unroll
            for (int it = 0; it < 2; ++it) {
                int idx  = tid + it * 256;
                int half = idx >> 8;
                int rsd  = idx & 255;
                int row  = rsd >> 2, ch = rsd & 3;
                const __nv_bfloat16* src =
                    (half ? Wl : Wh) + ((size_t)e * O + n0 + row) * IDIM + i0 + ch * 8;
                uint32_t dst = dbase + half * BSZ + row * RS + ch * 16;
                CP_ASYNC16(dst, src);
            }
        }
        CP_COMMIT();
    };

    float acc[2][4][4] = {};

    load_chunk(0, 0);
    for (int c = 0; c < nc; ++c) {
        int buf = c & 1;
        if (c + 1 < nc) { load_chunk(c + 1, (c + 1) & 1); CP_WAIT1(); }
        else            { CP_WAIT0(); }
        __syncthreads();

        uint32_t stg = sb + buf * STAGE;
        // ldmatrix addresses
        int arow  = lane & 15;
        int acolb = (lane >> 4) * 16;
        int nrow  = (lane & 7) + ((lane >> 4) << 3);
        int bcolb = ((lane >> 3) & 1) * 16;

        #pragma unroll
        for (int kk = 0; kk < 2; ++kk) {
            uint32_t a_h[2][4], a_l[2][4];
            #pragma unroll
            for (int mt = 0; mt < 2; ++mt) {
                uint32_t ra = stg + AHo + (wy*32 + mt*16 + arow) * RS + kk*32 + acolb;
                LDSM4(a_h[mt], ra);
                LDSM4(a_l[mt], ra + (ALo - AHo));
            }
            uint32_t b_h[2][4], b_l[2][4];
            #pragma unroll
            for (int p = 0; p < 2; ++p) {
                uint32_t rb = stg + BHo + (wx*32 + p*16 + nrow) * RS + kk*32 + bcolb;
                LDSM4(b_h[p], rb);
                LDSM4(b_l[p], rb + BSZ);
            }
            #pragma unroll
            for (int mt = 0; mt < 2; ++mt)
                #pragma unroll
                for (int p = 0; p < 2; ++p)
                    #pragma unroll
                    for (int h = 0; h < 2; ++h) {
                        float* d = acc[mt][p*2 + h];
                        MMA16816(d, a_h[mt], b_h[p][h*2], b_h[p][h*2+1]);
                        MMA16816(d, a_h[mt], b_l[p][h*2], b_l[p][h*2+1]);
                        MMA16816(d, a_l[mt], b_h[p][h*2], b_h[p][h*2+1]);
                    }
        }
        __syncthreads();
    }

    // ---- epilogue: atomicAdd into bias-initialized out ----
    int g   = lane >> 2;
    int tig = lane & 3;
    #pragma unroll
    for (int mt = 0; mt < 2; ++mt)
        #pragma unroll
        for (int nt = 0; nt < 4; ++nt) {
            int row = m0 + wy*32 + mt*16 + g;
            int col = n0 + wx*32 + nt*8 + tig*2;
            float* p0 = out + (size_t)row * O + col;
            atomicAdd(p0,     acc[mt][nt][0]);
            atomicAdd(p0 + 1, acc[mt][nt][1]);
            float* p1 = p0 + (size_t)8 * O;
            atomicAdd(p1,     acc[mt][nt][2]);
            atomicAdd(p1 + 1, acc[mt][nt][3]);
        }
}

// ===========================================================================
extern "C" void kernel_launch(void* const* d_in, const int* in_sizes, int n_in,
                              void* d_out, int out_size) {
    const float* m0    = (const float*)d_in[0];
    const float* x0    = (const float*)d_in[1];
    const float* mW1   = (const float*)d_in[2];
    const float* mb1   = (const float*)d_in[3];
    const float* mg1   = (const float*)d_in[4];
    const float* mbe1  = (const float*)d_in[5];
    const float* ma1   = (const float*)d_in[6];
    const float* mW2   = (const float*)d_in[7];
    const float* mb2   = (const float*)d_in[8];
    const float* mg2   = (const float*)d_in[9];
    const float* mbe2  = (const float*)d_in[10];
    const float* ma2   = (const float*)d_in[11];
    const float* mW3   = (const float*)d_in[12];
    const float* mb3   = (const float*)d_in[13];
    const float* mg3   = (const float*)d_in[14];
    const float* mbe3  = (const float*)d_in[15];
    const float* ma3   = (const float*)d_in[16];
    const float* Wenc0 = (const float*)d_in[17];
    const float* benc0 = (const float*)d_in[18];
    const float* Wenc1 = (const float*)d_in[19];
    const float* benc1 = (const float*)d_in[20];
    const float* Wdec0 = (const float*)d_in[21];
    const float* bdec0 = (const float*)d_in[22];
    const float* Wdec1 = (const float*)d_in[23];
    const float* bdec1 = (const float*)d_in[24];
    const float* bng   = (const float*)d_in[25];
    const float* bnb   = (const float*)d_in[26];
    const float* aP    = (const float*)d_in[27];
    float* out = (float*)d_out;

    float *b0, *b1, *b2, *wb;
    __nv_bfloat16 *Wh, *Wl;
    cudaGetSymbolAddress((void**)&b0, g_buf0);
    cudaGetSymbolAddress((void**)&b1, g_buf1);
    cudaGetSymbolAddress((void**)&b2, g_buf2);
    cudaGetSymbolAddress((void**)&wb, g_w);
    cudaGetSymbolAddress((void**)&Wh, g_Wh);
    cudaGetSymbolAddress((void**)&Wl, g_Wl);

    const int SMEM = 61440;
    cudaFuncSetAttribute(expert_mma_kernel<64>,
                         cudaFuncAttributeMaxDynamicSharedMemorySize, SMEM);
    cudaFuncSetAttribute(expert_mma_kernel<256>,
                         cudaFuncAttributeMaxDynamicSharedMemorySize, SMEM);

    // ---- pre-split expert weights to bf16 hi/lo ----
    split_w_kernel<<<1024, 256>>>(Wenc0, Wh + OFF_ENC0, Wl + OFF_ENC0, 1048576 / 4);
    split_w_kernel<<<4096, 256>>>(Wenc1, Wh + OFF_ENC1, Wl + OFF_ENC1, 4194304 / 4);
    split_w_kernel<<<4096, 256>>>(Wdec0, Wh + OFF_DEC0, Wl + OFF_DEC0, 4194304 / 4);
    split_w_kernel<<<1024, 256>>>(Wdec1, Wh + OFF_DEC1, Wl + OFF_DEC1, 1048576 / 4);

    // ---- MNet: 3x (Linear -> BN -> PReLU) -> w [4096,64] ----
    gemm_bias_kernel<<<dim3(4, 64), 256>>>(m0, mW1, mb1, b0, 128, 256);
    bn_prelu_kernel<<<128, 256>>>(b0, mg1, mbe1, ma1, 256);
    gemm_bias_kernel<<<dim3(2, 64), 256>>>(b0, mW2, mb2, b1, 256, 128);
    bn_prelu_kernel<<<64, 256>>>(b1, mg2, mbe2, ma2, 128);
    gemm_bias_kernel<<<dim3(1, 64), 256>>>(b1, mW3, mb3, wb, 128, 64);
    bn_prelu_kernel<<<32, 256>>>(wb, mg3, mbe3, ma3, 64);

    zero_sum_kernel<<<1, 1>>>();
    reduce_w_kernel<<<64, 256>>>(wb);
    inv_kernel<<<1, 1>>>();

    // ---- encoder layer 0: x0[4096,64] -> b2[4096,256] ----
    bias_combine_kernel<<<BATCH * 256 / 256, 256>>>(wb, benc0, b2, 256);
    expert_mma_kernel<64><<<dim3(4, 32, 2), 256, SMEM>>>(
        x0, Wh + OFF_ENC0, Wl + OFF_ENC0, wb, b2, 256, 32);
    bn_prelu_kernel<<<128, 256>>>(b2, bng, bnb, aP, 256);

    // ---- encoder layer 1: b2 -> b0 ----
    bias_combine_kernel<<<BATCH * 256 / 256, 256>>>(wb, benc1, b0, 256);
    expert_mma_kernel<256><<<dim3(4, 32, 4), 256, SMEM>>>(
        b2, Wh + OFF_ENC1, Wl + OFF_ENC1, wb, b0, 256, 16);
    bn_prelu_kernel<<<128, 256>>>(b0, bng, bnb, aP, 256);

    // ---- decoder layer 0: b0 -> b1 ----
    bias_combine_kernel<<<BATCH * 256 / 256, 256>>>(wb, bdec0, b1, 256);
    expert_mma_kernel<256><<<dim3(4, 32, 4), 256, SMEM>>>(
        b0, Wh + OFF_DEC0, Wl + OFF_DEC0, wb, b1, 256, 16);
    bn_prelu_kernel<<<128, 256>>>(b1, bng, bnb, aP, 256);

    // ---- decoder layer 1 (no BN/PReLU): b1 -> out [4096,64] ----
    bias_combine_kernel<<<BATCH * 64 / 256, 256>>>(wb, bdec1, out, 64);
    expert_mma_kernel<256><<<dim3(1, 32, 8), 256, SMEM>>>(
        b1, Wh + OFF_DEC1, Wl + OFF_DEC1, wb, out, 64, 8);
}

// round 5
// speedup vs baseline: 2.4147x; 1.1914x over previous
#include <cuda_runtime.h>
#include <cuda_bf16.h>
#include <cstdint>

#define BATCH 4096
#define NE    64
#define EPSV  1e-5f

// ===================== device scratch (no runtime alloc) ====================
__device__ __align__(16) float g_buf0[BATCH * 256];
__device__ __align__(16) float g_buf1[BATCH * 256];
__device__ __align__(16) float g_buf2[BATCH * 256];
__device__ __align__(16) float g_w   [BATCH * NE];
__device__ float g_sum, g_inv;

// activation bf16 hi/lo (max 4096 x 256)
__device__ __align__(16) __nv_bfloat16 g_Zh[BATCH * 256];
__device__ __align__(16) __nv_bfloat16 g_Zl[BATCH * 256];

// split-bf16 weights: enc0(1M) enc1(4M) dec0(4M) dec1(1M) = 10.5M elems
#define OFF_ENC0 0
#define OFF_ENC1 1048576
#define OFF_DEC0 5242880
#define OFF_DEC1 9437184
#define W_TOTAL  10485760
__device__ __align__(16) __nv_bfloat16 g_Wh[W_TOTAL];
__device__ __align__(16) __nv_bfloat16 g_Wl[W_TOTAL];

// ===================== PTX helpers (base sm_103 target only) ===============
__device__ __forceinline__ uint32_t smem_u32(const void* p) {
    uint32_t a;
    asm("{ .reg .u64 t; cvta.to.shared.u64 t, %1; cvt.u32.u64 %0, t; }"
        : "=r"(a) : "l"(p));
    return a;
}

#define LDSM4(r, a) \
    asm volatile("ldmatrix.sync.aligned.m8n8.x4.shared.b16 {%0,%1,%2,%3}, [%4];" \
        : "=r"((r)[0]), "=r"((r)[1]), "=r"((r)[2]), "=r"((r)[3]) : "r"(a))

#define MMA16816(d, a, b0v, b1v) \
    asm volatile("mma.sync.aligned.m16n8k16.row.col.f32.bf16.bf16.f32 " \
        "{%0,%1,%2,%3}, {%4,%5,%6,%7}, {%8,%9}, {%0,%1,%2,%3};" \
        : "+f"((d)[0]), "+f"((d)[1]), "+f"((d)[2]), "+f"((d)[3]) \
        : "r"((a)[0]), "r"((a)[1]), "r"((a)[2]), "r"((a)[3]), "r"(b0v), "r"(b1v))

#define CP_ASYNC16(dst, src) \
    asm volatile("cp.async.cg.shared.global [%0], [%1], 16;" :: "r"(dst), "l"(src))
#define CP_COMMIT() asm volatile("cp.async.commit_group;" ::: "memory")
#define CP_WAIT1()  asm volatile("cp.async.wait_group 1;" ::: "memory")
#define CP_WAIT0()  asm volatile("cp.async.wait_group 0;" ::: "memory")

// ============== split fp32 -> bf16 hi/lo (8 elems/thread) ==================
__global__ __launch_bounds__(256)
void split_w_kernel(const float* __restrict__ W, __nv_bfloat16* __restrict__ Wh,
                    __nv_bfloat16* __restrict__ Wl, int n8) {
    int i = blockIdx.x * 256 + threadIdx.x;
    if (i >= n8) return;
    float4 v0 = reinterpret_cast<const float4*>(W)[2 * i];
    float4 v1 = reinterpret_cast<const float4*>(W)[2 * i + 1];
    float f[8] = {v0.x, v0.y, v0.z, v0.w, v1.x, v1.y, v1.z, v1.w};
    uint32_t hw[4], lw[4];
    #pragma unroll
    for (int j = 0; j < 4; ++j) {
        __nv_bfloat162 h2 = __floats2bfloat162_rn(f[2*j], f[2*j+1]);
        float q0 = f[2*j]   - __low2float(h2);
        float q1 = f[2*j+1] - __high2float(h2);
        __nv_bfloat162 l2 = __floats2bfloat162_rn(q0, q1);
        hw[j] = *reinterpret_cast<uint32_t*>(&h2);
        lw[j] = *reinterpret_cast<uint32_t*>(&l2);
    }
    reinterpret_cast<uint4*>(Wh)[i] = make_uint4(hw[0], hw[1], hw[2], hw[3]);
    reinterpret_cast<uint4*>(Wl)[i] = make_uint4(lw[0], lw[1], lw[2], lw[3]);
}

// ===================== small GEMM (MNet, fp32 SIMT) ========================
__global__ __launch_bounds__(256)
void gemm_bias_kernel(const float* __restrict__ X, const float* __restrict__ W,
                      const float* __restrict__ bias, float* __restrict__ C,
                      int K, int N) {
    const int BM = 64, BN = 64, BK = 16, TM = 4, TN = 4;
    __shared__ __align__(16) float As[BK][BM];
    __shared__ __align__(16) float Bs[BK][BN];
    int tid  = threadIdx.x;
    int n0   = blockIdx.x * BN;
    int m0   = blockIdx.y * BM;
    int tn   = tid & 15, tm = tid >> 4;
    int row0 = tm * TM, col0 = tn * TN;
    int lr   = tid >> 2, ls = tid & 3;
    float acc[TM][TN] = {};
    for (int k0 = 0; k0 < K; k0 += BK) {
        float4 av = *reinterpret_cast<const float4*>(&X[(size_t)(m0 + lr) * K + k0 + ls * 4]);
        As[ls*4+0][lr] = av.x; As[ls*4+1][lr] = av.y; As[ls*4+2][lr] = av.z; As[ls*4+3][lr] = av.w;
        float4 bv = *reinterpret_cast<const float4*>(&W[(size_t)(n0 + lr) * K + k0 + ls * 4]);
        Bs[ls*4+0][lr] = bv.x; Bs[ls*4+1][lr] = bv.y; Bs[ls*4+2][lr] = bv.z; Bs[ls*4+3][lr] = bv.w;
        __syncthreads();
        #pragma unroll
        for (int kk = 0; kk < BK; ++kk) {
            float a[TM], b[TN];
            float4 va = *reinterpret_cast<const float4*>(&As[kk][row0]);
            a[0]=va.x; a[1]=va.y; a[2]=va.z; a[3]=va.w;
            float4 vb = *reinterpret_cast<const float4*>(&Bs[kk][col0]);
            b[0]=vb.x; b[1]=vb.y; b[2]=vb.z; b[3]=vb.w;
            #pragma unroll
            for (int i = 0; i < TM; i++)
                #pragma unroll
                for (int j = 0; j < TN; j++)
                    acc[i][j] = fmaf(a[i], b[j], acc[i][j]);
        }
        __syncthreads();
    }
    #pragma unroll
    for (int i = 0; i < TM; i++)
        #pragma unroll
        for (int j = 0; j < TN; j++)
            C[(size_t)(m0 + row0 + i) * N + n0 + col0 + j] = acc[i][j] + bias[n0 + col0 + j];
}

// ============ BN + PReLU in place (MNet path, fp32 out) ====================
__global__ __launch_bounds__(256)
void bn_prelu_kernel(float* __restrict__ X, const float* __restrict__ g,
                     const float* __restrict__ be, const float* __restrict__ aP,
                     int C) {
    __shared__ float s1[256], s2[256];
    int tid = threadIdx.x;
    int col = blockIdx.x * 2 + (tid & 1);
    int r0  = tid >> 1;
    float sum = 0.f, sq = 0.f;
    for (int r = r0; r < BATCH; r += 128) {
        float v = X[(size_t)r * C + col];
        sum += v; sq += v * v;
    }
    s1[tid] = sum; s2[tid] = sq;
    __syncthreads();
    #pragma unroll
    for (int off = 128; off >= 2; off >>= 1) {
        if (tid < off) { s1[tid] += s1[tid + off]; s2[tid] += s2[tid + off]; }
        __syncthreads();
    }
    float mean = s1[tid & 1] * (1.f / BATCH);
    float var  = s2[tid & 1] * (1.f / BATCH) - mean * mean;
    float sc   = g[col] * rsqrtf(var + EPSV);
    float sh   = be[col] - mean * sc;
    float a    = aP[0];
    for (int r = r0; r < BATCH; r += 128) {
        float v = X[(size_t)r * C + col] * sc + sh;
        X[(size_t)r * C + col] = (v >= 0.f) ? v : a * v;
    }
}

// ====== BN + PReLU fused with bf16 hi/lo split (expert path) ===============
// reads X fp32, writes only Zh/Zl (X left untouched).
__global__ __launch_bounds__(256)
void bn_prelu_split_kernel(const float* __restrict__ X, const float* __restrict__ g,
                           const float* __restrict__ be, const float* __restrict__ aP,
                           int C, __nv_bfloat16* __restrict__ Zh,
                           __nv_bfloat16* __restrict__ Zl) {
    __shared__ float s1[256], s2[256];
    int tid = threadIdx.x;
    int col = blockIdx.x * 2 + (tid & 1);
    int r0  = tid >> 1;
    float sum = 0.f, sq = 0.f;
    for (int r = r0; r < BATCH; r += 128) {
        float v = X[(size_t)r * C + col];
        sum += v; sq += v * v;
    }
    s1[tid] = sum; s2[tid] = sq;
    __syncthreads();
    #pragma unroll
    for (int off = 128; off >= 2; off >>= 1) {
        if (tid < off) { s1[tid] += s1[tid + off]; s2[tid] += s2[tid + off]; }
        __syncthreads();
    }
    float mean = s1[tid & 1] * (1.f / BATCH);
    float var  = s2[tid & 1] * (1.f / BATCH) - mean * mean;
    float sc   = g[col] * rsqrtf(var + EPSV);
    float sh   = be[col] - mean * sc;
    float a    = aP[0];
    for (int r = r0; r < BATCH; r += 128) {
        float v = X[(size_t)r * C + col] * sc + sh;
        v = (v >= 0.f) ? v : a * v;
        __nv_bfloat16 h = __float2bfloat16_rn(v);
        __nv_bfloat16 l = __float2bfloat16_rn(v - __bfloat162float(h));
        Zh[(size_t)r * C + col] = h;
        Zl[(size_t)r * C + col] = l;
    }
}

// ===================== global sum -> inverse ================================
__global__ void zero_sum_kernel() { g_sum = 0.f; }

__global__ __launch_bounds__(256)
void reduce_w_kernel(const float* __restrict__ w) {
    __shared__ float s[256];
    int tid = threadIdx.x;
    float a = 0.f;
    for (int i = blockIdx.x * 256 + tid; i < BATCH * NE; i += gridDim.x * 256) a += w[i];
    s[tid] = a; __syncthreads();
    #pragma unroll
    for (int off = 128; off; off >>= 1) {
        if (tid < off) s[tid] += s[tid + off];
        __syncthreads();
    }
    if (tid == 0) atomicAdd(&g_sum, s[0]);
}

__global__ void inv_kernel() { g_inv = 1.f / g_sum; }

// ============ out[b,o] = inv * sum_e w[b,e]*bias[e,o] (acc init) ===========
__global__ __launch_bounds__(256)
void bias_combine_kernel(const float* __restrict__ w, const float* __restrict__ bias,
                         float* __restrict__ out, int O) {
    int idx = blockIdx.x * 256 + threadIdx.x;
    int b = idx / O, o = idx - b * O;
    float inv = g_inv;
    const float* wr = w + (size_t)b * NE;
    float acc = 0.f;
    #pragma unroll 8
    for (int e = 0; e < NE; e++) acc = fmaf(wr[e], bias[(size_t)e * O + o], acc);
    out[idx] = acc * inv;
}

// ===================== mma.sync expert GEMM (split-bf16) ===================
// accO[b,o] = sum_e (w[b,e]*inv) * (z[b,:] . W[e,o,:])
// Pure cp.async mainloop (A = pre-split Zh/Zl, B = pre-split Wh/Wl);
// per-expert register accumulator scaled by w at expert boundaries.
// BM=128, BN=64, BK=32; 8 warps (4M x 2N); split-K over experts + atomicAdd.
template<int IDIM>
__global__ __launch_bounds__(256, 2)
void expert_mma_kernel(const __nv_bfloat16* __restrict__ Zh,
                       const __nv_bfloat16* __restrict__ Zl,
                       const __nv_bfloat16* __restrict__ Wh,
                       const __nv_bfloat16* __restrict__ Wl,
                       const float* __restrict__ w,
                       float* __restrict__ out,
                       int O, int eper) {
    constexpr int RS    = 80;                 // padded row stride (bytes)
    constexpr int AHo   = 0;
    constexpr int ALo   = 128 * RS;           // 10240
    constexpr int BHo   = 2 * 128 * RS;       // 20480
    constexpr int BSZ   = 64 * RS;            // 5120
    constexpr int STAGE = BHo + 2 * BSZ;      // 30720
    constexpr int CPE   = IDIM / 32;          // chunks per expert

    extern __shared__ char smem[];
    uint32_t sb = smem_u32(smem);

    int tid  = threadIdx.x;
    int lane = tid & 31, wid = tid >> 5;
    int wy = wid >> 1, wx = wid & 1;          // 4 M-warps x 2 N-warps
    int m0 = blockIdx.y * 128;
    int n0 = blockIdx.x * 64;
    int e0 = blockIdx.z * eper;
    float inv = g_inv;
    const int nc = eper * CPE;

    auto load_chunk = [&](int c, int buf) {
        int e  = e0 + c / CPE;
        int i0 = (c % CPE) * 32;
        uint32_t stg = sb + buf * STAGE;
        // A: Zh/Zl tile 128 rows x 32 bf16 (hi+lo) = 1024 x 16B
        #pragma unroll
        for (int it = 0; it < 4; ++it) {
            int idx  = tid + it * 256;
            int half = idx >> 9;
            int rsd  = idx & 511;
            int row  = rsd >> 2, ch = rsd & 3;
            const __nv_bfloat16* src =
                (half ? Zl : Zh) + (size_t)(m0 + row) * IDIM + i0 + ch * 8;
            CP_ASYNC16(stg + half * (ALo - AHo) + row * RS + ch * 16, src);
        }
        // B: Wh/Wl tile 64 rows x 32 bf16 (hi+lo) = 512 x 16B
        #pragma unroll
        for (int it = 0; it < 2; ++it) {
            int idx  = tid + it * 256;
            int half = idx >> 8;
            int rsd  = idx & 255;
            int row  = rsd >> 2, ch = rsd & 3;
            const __nv_bfloat16* src =
                (half ? Wl : Wh) + ((size_t)e * O + n0 + row) * IDIM + i0 + ch * 8;
            CP_ASYNC16(stg + BHo + half * BSZ + row * RS + ch * 16, src);
        }
        CP_COMMIT();
    };

    float accE[2][4][4] = {};   // per-expert
    float accO[2][4][4] = {};   // scaled output accumulator
    int g   = lane >> 2;
    int tig = lane & 3;

    load_chunk(0, 0);
    for (int c = 0; c < nc; ++c) {
        int buf = c & 1;
        if (c + 1 < nc) { load_chunk(c + 1, (c + 1) & 1); CP_WAIT1(); }
        else            { CP_WAIT0(); }
        __syncthreads();

        uint32_t stg  = sb + buf * STAGE;
        int arow  = lane & 15;
        int acolb = (lane >> 4) * 16;
        int nrow  = (lane & 7) + ((lane >> 4) << 3);
        int bcolb = ((lane >> 3) & 1) * 16;

        #pragma unroll
        for (int kk = 0; kk < 2; ++kk) {
            uint32_t a_h[2][4], a_l[2][4];
            #pragma unroll
            for (int mt = 0; mt < 2; ++mt) {
                uint32_t ra = stg + AHo + (wy*32 + mt*16 + arow) * RS + kk*32 + acolb;
                LDSM4(a_h[mt], ra);
                LDSM4(a_l[mt], ra + (ALo - AHo));
            }
            uint32_t b_h[2][4], b_l[2][4];
            #pragma unroll
            for (int p = 0; p < 2; ++p) {
                uint32_t rb = stg + BHo + (wx*32 + p*16 + nrow) * RS + kk*32 + bcolb;
                LDSM4(b_h[p], rb);
                LDSM4(b_l[p], rb + BSZ);
            }
            #pragma unroll
            for (int mt = 0; mt < 2; ++mt)
                #pragma unroll
                for (int p = 0; p < 2; ++p)
                    #pragma unroll
                    for (int h = 0; h < 2; ++h) {
                        float* d = accE[mt][p*2 + h];
                        MMA16816(d, a_h[mt], b_h[p][h*2], b_h[p][h*2+1]);
                        MMA16816(d, a_h[mt], b_l[p][h*2], b_l[p][h*2+1]);
                        MMA16816(d, a_l[mt], b_h[p][h*2], b_h[p][h*2+1]);
                    }
        }
        __syncthreads();

        // expert boundary: fold w[b,e]*inv into output accumulator
        if (((c + 1) & (CPE - 1)) == 0) {
            int e = e0 + c / CPE;
            float wv0[2], wv1[2];
            #pragma unroll
            for (int mt = 0; mt < 2; ++mt) {
                int r = m0 + wy*32 + mt*16 + g;
                wv0[mt] = w[(size_t)r * NE + e] * inv;
                wv1[mt] = w[(size_t)(r + 8) * NE + e] * inv;
            }
            #pragma unroll
            for (int mt = 0; mt < 2; ++mt)
                #pragma unroll
                for (int nt = 0; nt < 4; ++nt) {
                    accO[mt][nt][0] = fmaf(wv0[mt], accE[mt][nt][0], accO[mt][nt][0]);
                    accO[mt][nt][1] = fmaf(wv0[mt], accE[mt][nt][1], accO[mt][nt][1]);
                    accO[mt][nt][2] = fmaf(wv1[mt], accE[mt][nt][2], accO[mt][nt][2]);
                    accO[mt][nt][3] = fmaf(wv1[mt], accE[mt][nt][3], accO[mt][nt][3]);
                    accE[mt][nt][0] = 0.f; accE[mt][nt][1] = 0.f;
                    accE[mt][nt][2] = 0.f; accE[mt][nt][3] = 0.f;
                }
        }
    }

    // ---- epilogue: atomicAdd into bias-initialized out ----
    #pragma unroll
    for (int mt = 0; mt < 2; ++mt)
        #pragma unroll
        for (int nt = 0; nt < 4; ++nt) {
            int row = m0 + wy*32 + mt*16 + g;
            int col = n0 + wx*32 + nt*8 + tig*2;
            float* p0 = out + (size_t)row * O + col;
            atomicAdd(p0,     accO[mt][nt][0]);
            atomicAdd(p0 + 1, accO[mt][nt][1]);
            float* p1 = p0 + (size_t)8 * O;
            atomicAdd(p1,     accO[mt][nt][2]);
            atomicAdd(p1 + 1, accO[mt][nt][3]);
        }
}

// ===========================================================================
extern "C" void kernel_launch(void* const* d_in, const int* in_sizes, int n_in,
                              void* d_out, int out_size) {
    const float* m0    = (const float*)d_in[0];
    const float* x0    = (const float*)d_in[1];
    const float* mW1   = (const float*)d_in[2];
    const float* mb1   = (const float*)d_in[3];
    const float* mg1   = (const float*)d_in[4];
    const float* mbe1  = (const float*)d_in[5];
    const float* ma1   = (const float*)d_in[6];
    const float* mW2   = (const float*)d_in[7];
    const float* mb2   = (const float*)d_in[8];
    const float* mg2   = (const float*)d_in[9];
    const float* mbe2  = (const float*)d_in[10];
    const float* ma2   = (const float*)d_in[11];
    const float* mW3   = (const float*)d_in[12];
    const float* mb3   = (const float*)d_in[13];
    const float* mg3   = (const float*)d_in[14];
    const float* mbe3  = (const float*)d_in[15];
    const float* ma3   = (const float*)d_in[16];
    const float* Wenc0 = (const float*)d_in[17];
    const float* benc0 = (const float*)d_in[18];
    const float* Wenc1 = (const float*)d_in[19];
    const float* benc1 = (const float*)d_in[20];
    const float* Wdec0 = (const float*)d_in[21];
    const float* bdec0 = (const float*)d_in[22];
    const float* Wdec1 = (const float*)d_in[23];
    const float* bdec1 = (const float*)d_in[24];
    const float* bng   = (const float*)d_in[25];
    const float* bnb   = (const float*)d_in[26];
    const float* aP    = (const float*)d_in[27];
    float* out = (float*)d_out;

    float *b0, *b1, *b2, *wb;
    __nv_bfloat16 *Wh, *Wl, *Zh, *Zl;
    cudaGetSymbolAddress((void**)&b0, g_buf0);
    cudaGetSymbolAddress((void**)&b1, g_buf1);
    cudaGetSymbolAddress((void**)&b2, g_buf2);
    cudaGetSymbolAddress((void**)&wb, g_w);
    cudaGetSymbolAddress((void**)&Wh, g_Wh);
    cudaGetSymbolAddress((void**)&Wl, g_Wl);
    cudaGetSymbolAddress((void**)&Zh, g_Zh);
    cudaGetSymbolAddress((void**)&Zl, g_Zl);

    const int SMEM = 61440;
    cudaFuncSetAttribute(expert_mma_kernel<64>,
                         cudaFuncAttributeMaxDynamicSharedMemorySize, SMEM);
    cudaFuncSetAttribute(expert_mma_kernel<256>,
                         cudaFuncAttributeMaxDynamicSharedMemorySize, SMEM);

    // ---- pre-split expert weights to bf16 hi/lo ----
    split_w_kernel<<< 512, 256>>>(Wenc0, Wh + OFF_ENC0, Wl + OFF_ENC0, 1048576 / 8);
    split_w_kernel<<<2048, 256>>>(Wenc1, Wh + OFF_ENC1, Wl + OFF_ENC1, 4194304 / 8);
    split_w_kernel<<<2048, 256>>>(Wdec0, Wh + OFF_DEC0, Wl + OFF_DEC0, 4194304 / 8);
    split_w_kernel<<< 512, 256>>>(Wdec1, Wh + OFF_DEC1, Wl + OFF_DEC1, 1048576 / 8);

    // ---- MNet: 3x (Linear -> BN -> PReLU) -> w [4096,64] ----
    gemm_bias_kernel<<<dim3(4, 64), 256>>>(m0, mW1, mb1, b0, 128, 256);
    bn_prelu_kernel<<<128, 256>>>(b0, mg1, mbe1, ma1, 256);
    gemm_bias_kernel<<<dim3(2, 64), 256>>>(b0, mW2, mb2, b1, 256, 128);
    bn_prelu_kernel<<<64, 256>>>(b1, mg2, mbe2, ma2, 128);
    gemm_bias_kernel<<<dim3(1, 64), 256>>>(b1, mW3, mb3, wb, 128, 64);
    bn_prelu_kernel<<<32, 256>>>(wb, mg3, mbe3, ma3, 64);

    zero_sum_kernel<<<1, 1>>>();
    reduce_w_kernel<<<64, 256>>>(wb);
    inv_kernel<<<1, 1>>>();

    // ---- encoder layer 0: x0[4096,64] -> b2[4096,256] ----
    split_w_kernel<<<128, 256>>>(x0, Zh, Zl, BATCH * 64 / 8);
    bias_combine_kernel<<<BATCH * 256 / 256, 256>>>(wb, benc0, b2, 256);
    expert_mma_kernel<64><<<dim3(4, 32, 2), 256, SMEM>>>(
        Zh, Zl, Wh + OFF_ENC0, Wl + OFF_ENC0, wb, b2, 256, 32);
    bn_prelu_split_kernel<<<128, 256>>>(b2, bng, bnb, aP, 256, Zh, Zl);

    // ---- encoder layer 1: -> b0 ----
    bias_combine_kernel<<<BATCH * 256 / 256, 256>>>(wb, benc1, b0, 256);
    expert_mma_kernel<256><<<dim3(4, 32, 4), 256, SMEM>>>(
        Zh, Zl, Wh + OFF_ENC1, Wl + OFF_ENC1, wb, b0, 256, 16);
    bn_prelu_split_kernel<<<128, 256>>>(b0, bng, bnb, aP, 256, Zh, Zl);

    // ---- decoder layer 0: -> b1 ----
    bias_combine_kernel<<<BATCH * 256 / 256, 256>>>(wb, bdec0, b1, 256);
    expert_mma_kernel<256><<<dim3(4, 32, 4), 256, SMEM>>>(
        Zh, Zl, Wh + OFF_DEC0, Wl + OFF_DEC0, wb, b1, 256, 16);
    bn_prelu_split_kernel<<<128, 256>>>(b1, bng, bnb, aP, 256, Zh, Zl);

    // ---- decoder layer 1 (no BN/PReLU): -> out [4096,64] ----
    bias_combine_kernel<<<BATCH * 64 / 256, 256>>>(wb, bdec1, out, 64);
    expert_mma_kernel<256><<<dim3(1, 32, 8), 256, SMEM>>>(
        Zh, Zl, Wh + OFF_DEC1, Wl + OFF_DEC1, wb, out, 64, 8);
}

// round 6
// speedup vs baseline: 2.5382x; 1.0511x over previous
#include <cuda_runtime.h>
#include <cuda_bf16.h>
#include <cstdint>

#define BATCH 4096
#define NE    64
#define EPSV  1e-5f

// ===================== device scratch (no runtime alloc) ====================
__device__ __align__(16) float g_buf0[BATCH * 256];
__device__ __align__(16) float g_buf1[BATCH * 256];
__device__ __align__(16) float g_buf2[BATCH * 256];
__device__ __align__(16) float g_w   [BATCH * NE];
__device__ float g_sum, g_inv;

// activation bf16 hi/lo (max 4096 x 256)
__device__ __align__(16) __nv_bfloat16 g_Zh[BATCH * 256];
__device__ __align__(16) __nv_bfloat16 g_Zl[BATCH * 256];

// split-bf16 weights: enc0(1M) enc1(4M) dec0(4M) dec1(1M) = 10.5M elems
#define OFF_ENC0 0
#define OFF_ENC1 1048576
#define OFF_DEC0 5242880
#define OFF_DEC1 9437184
#define W_TOTAL  10485760
__device__ __align__(16) __nv_bfloat16 g_Wh[W_TOTAL];
__device__ __align__(16) __nv_bfloat16 g_Wl[W_TOTAL];

// ===================== PTX helpers (base sm_103 target only) ===============
__device__ __forceinline__ uint32_t smem_u32(const void* p) {
    uint32_t a;
    asm("{ .reg .u64 t; cvta.to.shared.u64 t, %1; cvt.u32.u64 %0, t; }"
        : "=r"(a) : "l"(p));
    return a;
}

#define LDSM4(r, a) \
    asm volatile("ldmatrix.sync.aligned.m8n8.x4.shared.b16 {%0,%1,%2,%3}, [%4];" \
        : "=r"((r)[0]), "=r"((r)[1]), "=r"((r)[2]), "=r"((r)[3]) : "r"(a))

#define MMA16816(d, a, b0v, b1v) \
    asm volatile("mma.sync.aligned.m16n8k16.row.col.f32.bf16.bf16.f32 " \
        "{%0,%1,%2,%3}, {%4,%5,%6,%7}, {%8,%9}, {%0,%1,%2,%3};" \
        : "+f"((d)[0]), "+f"((d)[1]), "+f"((d)[2]), "+f"((d)[3]) \
        : "r"((a)[0]), "r"((a)[1]), "r"((a)[2]), "r"((a)[3]), "r"(b0v), "r"(b1v))

#define CP_ASYNC16(dst, src) \
    asm volatile("cp.async.cg.shared.global [%0], [%1], 16;" :: "r"(dst), "l"(src))
#define CP_COMMIT() asm volatile("cp.async.commit_group;" ::: "memory")
#define CP_WAIT1()  asm volatile("cp.async.wait_group 1;" ::: "memory")
#define CP_WAIT0()  asm volatile("cp.async.wait_group 0;" ::: "memory")

// ============== split fp32 -> bf16 hi/lo (8 elems/thread) ==================
__global__ __launch_bounds__(256)
void split_w_kernel(const float* __restrict__ W, __nv_bfloat16* __restrict__ Wh,
                    __nv_bfloat16* __restrict__ Wl, int n8) {
    int i = blockIdx.x * 256 + threadIdx.x;
    if (i >= n8) return;
    float4 v0 = reinterpret_cast<const float4*>(W)[2 * i];
    float4 v1 = reinterpret_cast<const float4*>(W)[2 * i + 1];
    float f[8] = {v0.x, v0.y, v0.z, v0.w, v1.x, v1.y, v1.z, v1.w};
    uint32_t hw[4], lw[4];
    #pragma unroll
    for (int j = 0; j < 4; ++j) {
        __nv_bfloat162 h2 = __floats2bfloat162_rn(f[2*j], f[2*j+1]);
        float q0 = f[2*j]   - __low2float(h2);
        float q1 = f[2*j+1] - __high2float(h2);
        __nv_bfloat162 l2 = __floats2bfloat162_rn(q0, q1);
        hw[j] = *reinterpret_cast<uint32_t*>(&h2);
        lw[j] = *reinterpret_cast<uint32_t*>(&l2);
    }
    reinterpret_cast<uint4*>(Wh)[i] = make_uint4(hw[0], hw[1], hw[2], hw[3]);
    reinterpret_cast<uint4*>(Wl)[i] = make_uint4(lw[0], lw[1], lw[2], lw[3]);
}

// ===================== small GEMM (MNet, fp32 SIMT) ========================
__global__ __launch_bounds__(256)
void gemm_bias_kernel(const float* __restrict__ X, const float* __restrict__ W,
                      const float* __restrict__ bias, float* __restrict__ C,
                      int K, int N) {
    const int BM = 64, BN = 64, BK = 16, TM = 4, TN = 4;
    __shared__ __align__(16) float As[BK][BM];
    __shared__ __align__(16) float Bs[BK][BN];
    int tid  = threadIdx.x;
    int n0   = blockIdx.x * BN;
    int m0   = blockIdx.y * BM;
    int tn   = tid & 15, tm = tid >> 4;
    int row0 = tm * TM, col0 = tn * TN;
    int lr   = tid >> 2, ls = tid & 3;
    float acc[TM][TN] = {};
    for (int k0 = 0; k0 < K; k0 += BK) {
        float4 av = *reinterpret_cast<const float4*>(&X[(size_t)(m0 + lr) * K + k0 + ls * 4]);
        As[ls*4+0][lr] = av.x; As[ls*4+1][lr] = av.y; As[ls*4+2][lr] = av.z; As[ls*4+3][lr] = av.w;
        float4 bv = *reinterpret_cast<const float4*>(&W[(size_t)(n0 + lr) * K + k0 + ls * 4]);
        Bs[ls*4+0][lr] = bv.x; Bs[ls*4+1][lr] = bv.y; Bs[ls*4+2][lr] = bv.z; Bs[ls*4+3][lr] = bv.w;
        __syncthreads();
        #pragma unroll
        for (int kk = 0; kk < BK; ++kk) {
            float a[TM], b[TN];
            float4 va = *reinterpret_cast<const float4*>(&As[kk][row0]);
            a[0]=va.x; a[1]=va.y; a[2]=va.z; a[3]=va.w;
            float4 vb = *reinterpret_cast<const float4*>(&Bs[kk][col0]);
            b[0]=vb.x; b[1]=vb.y; b[2]=vb.z; b[3]=vb.w;
            #pragma unroll
            for (int i = 0; i < TM; i++)
                #pragma unroll
                for (int j = 0; j < TN; j++)
                    acc[i][j] = fmaf(a[i], b[j], acc[i][j]);
        }
        __syncthreads();
    }
    #pragma unroll
    for (int i = 0; i < TM; i++)
        #pragma unroll
        for (int j = 0; j < TN; j++)
            C[(size_t)(m0 + row0 + i) * N + n0 + col0 + j] = acc[i][j] + bias[n0 + col0 + j];
}

// ============ BN + PReLU in place (MNet path, fp32 out) ====================
__global__ __launch_bounds__(256)
void bn_prelu_kernel(float* __restrict__ X, const float* __restrict__ g,
                     const float* __restrict__ be, const float* __restrict__ aP,
                     int C) {
    __shared__ float s1[256], s2[256];
    int tid = threadIdx.x;
    int col = blockIdx.x * 2 + (tid & 1);
    int r0  = tid >> 1;
    float sum = 0.f, sq = 0.f;
    for (int r = r0; r < BATCH; r += 128) {
        float v = X[(size_t)r * C + col];
        sum += v; sq += v * v;
    }
    s1[tid] = sum; s2[tid] = sq;
    __syncthreads();
    #pragma unroll
    for (int off = 128; off >= 2; off >>= 1) {
        if (tid < off) { s1[tid] += s1[tid + off]; s2[tid] += s2[tid + off]; }
        __syncthreads();
    }
    float mean = s1[tid & 1] * (1.f / BATCH);
    float var  = s2[tid & 1] * (1.f / BATCH) - mean * mean;
    float sc   = g[col] * rsqrtf(var + EPSV);
    float sh   = be[col] - mean * sc;
    float a    = aP[0];
    for (int r = r0; r < BATCH; r += 128) {
        float v = X[(size_t)r * C + col] * sc + sh;
        X[(size_t)r * C + col] = (v >= 0.f) ? v : a * v;
    }
}

// ====== BN + PReLU fused with bf16 hi/lo split (expert path) ===============
__global__ __launch_bounds__(256)
void bn_prelu_split_kernel(const float* __restrict__ X, const float* __restrict__ g,
                           const float* __restrict__ be, const float* __restrict__ aP,
                           int C, __nv_bfloat16* __restrict__ Zh,
                           __nv_bfloat16* __restrict__ Zl) {
    __shared__ float s1[256], s2[256];
    int tid = threadIdx.x;
    int col = blockIdx.x * 2 + (tid & 1);
    int r0  = tid >> 1;
    float sum = 0.f, sq = 0.f;
    for (int r = r0; r < BATCH; r += 128) {
        float v = X[(size_t)r * C + col];
        sum += v; sq += v * v;
    }
    s1[tid] = sum; s2[tid] = sq;
    __syncthreads();
    #pragma unroll
    for (int off = 128; off >= 2; off >>= 1) {
        if (tid < off) { s1[tid] += s1[tid + off]; s2[tid] += s2[tid + off]; }
        __syncthreads();
    }
    float mean = s1[tid & 1] * (1.f / BATCH);
    float var  = s2[tid & 1] * (1.f / BATCH) - mean * mean;
    float sc   = g[col] * rsqrtf(var + EPSV);
    float sh   = be[col] - mean * sc;
    float a    = aP[0];
    for (int r = r0; r < BATCH; r += 128) {
        float v = X[(size_t)r * C + col] * sc + sh;
        v = (v >= 0.f) ? v : a * v;
        __nv_bfloat16 h = __float2bfloat16_rn(v);
        __nv_bfloat16 l = __float2bfloat16_rn(v - __bfloat162float(h));
        Zh[(size_t)r * C + col] = h;
        Zl[(size_t)r * C + col] = l;
    }
}

// ===================== global sum -> inverse ================================
__global__ void zero_sum_kernel() { g_sum = 0.f; }

__global__ __launch_bounds__(256)
void reduce_w_kernel(const float* __restrict__ w) {
    __shared__ float s[256];
    int tid = threadIdx.x;
    float a = 0.f;
    for (int i = blockIdx.x * 256 + tid; i < BATCH * NE; i += gridDim.x * 256) a += w[i];
    s[tid] = a; __syncthreads();
    #pragma unroll
    for (int off = 128; off; off >>= 1) {
        if (tid < off) s[tid] += s[tid + off];
        __syncthreads();
    }
    if (tid == 0) atomicAdd(&g_sum, s[0]);
}

__global__ void inv_kernel() { g_inv = 1.f / g_sum; }

// ============ out[b,o] = inv * sum_e w[b,e]*bias[e,o] (acc init) ===========
__global__ __launch_bounds__(256)
void bias_combine_kernel(const float* __restrict__ w, const float* __restrict__ bias,
                         float* __restrict__ out, int O) {
    int idx = blockIdx.x * 256 + threadIdx.x;
    int b = idx / O, o = idx - b * O;
    float inv = g_inv;
    const float* wr = w + (size_t)b * NE;
    float acc = 0.f;
    #pragma unroll 8
    for (int e = 0; e < NE; e++) acc = fmaf(wr[e], bias[(size_t)e * O + o], acc);
    out[idx] = acc * inv;
}

// ===================== mma.sync expert GEMM (split-bf16) ===================
// accO[b,o] = sum_e (w[b,e]*inv) * (z[b,:] . W[e,o,:])
// 3-stage cp.async ring, ONE __syncthreads per chunk.
// BM=128, BN=64, BK=32; 8 warps (4M x 2N); split-K over experts + atomicAdd.
template<int IDIM>
__global__ __launch_bounds__(256, 2)
void expert_mma_kernel(const __nv_bfloat16* __restrict__ Zh,
                       const __nv_bfloat16* __restrict__ Zl,
                       const __nv_bfloat16* __restrict__ Wh,
                       const __nv_bfloat16* __restrict__ Wl,
                       const float* __restrict__ w,
                       float* __restrict__ out,
                       int O, int eper) {
    constexpr int RS    = 80;                 // padded row stride (bytes)
    constexpr int AHo   = 0;
    constexpr int ALo   = 128 * RS;           // 10240
    constexpr int BHo   = 2 * 128 * RS;       // 20480
    constexpr int BSZ   = 64 * RS;            // 5120
    constexpr int STAGE = BHo + 2 * BSZ;      // 30720
    constexpr int CPE   = IDIM / 32;          // chunks per expert

    extern __shared__ char smem[];
    uint32_t sb = smem_u32(smem);

    int tid  = threadIdx.x;
    int lane = tid & 31, wid = tid >> 5;
    int wy = wid >> 1, wx = wid & 1;          // 4 M-warps x 2 N-warps
    int m0 = blockIdx.y * 128;
    int n0 = blockIdx.x * 64;
    int e0 = blockIdx.z * eper;
    float inv = g_inv;
    const int nc = eper * CPE;

    auto load_chunk = [&](int c, int buf) {
        int e  = e0 + c / CPE;
        int i0 = (c % CPE) * 32;
        uint32_t stg = sb + buf * STAGE;
        // A: Zh/Zl tile 128 rows x 32 bf16 (hi+lo) = 1024 x 16B
        #pragma unroll
        for (int it = 0; it < 4; ++it) {
            int idx  = tid + it * 256;
            int half = idx >> 9;
            int rsd  = idx & 511;
            int row  = rsd >> 2, ch = rsd & 3;
            const __nv_bfloat16* src =
                (half ? Zl : Zh) + (size_t)(m0 + row) * IDIM + i0 + ch * 8;
            CP_ASYNC16(stg + half * (ALo - AHo) + row * RS + ch * 16, src);
        }
        // B: Wh/Wl tile 64 rows x 32 bf16 (hi+lo) = 512 x 16B
        #pragma unroll
        for (int it = 0; it < 2; ++it) {
            int idx  = tid + it * 256;
            int half = idx >> 8;
            int rsd  = idx & 255;
            int row  = rsd >> 2, ch = rsd & 3;
            const __nv_bfloat16* src =
                (half ? Wl : Wh) + ((size_t)e * O + n0 + row) * IDIM + i0 + ch * 8;
            CP_ASYNC16(stg + BHo + half * BSZ + row * RS + ch * 16, src);
        }
        CP_COMMIT();
    };

    float accE[2][4][4] = {};   // per-expert
    float accO[2][4][4] = {};   // scaled output accumulator
    int g   = lane >> 2;
    int tig = lane & 3;

    // ldmatrix address constants
    int arow  = lane & 15;
    int acolb = (lane >> 4) * 16;
    int nrow  = (lane & 7) + ((lane >> 4) << 3);
    int bcolb = ((lane >> 3) & 1) * 16;

    // prologue: fill 2 of 3 stages
    load_chunk(0, 0);
    load_chunk(1, 1);

    int buf = 0;
    for (int c = 0; c < nc; ++c) {
        if (c + 1 < nc) CP_WAIT1(); else CP_WAIT0();
        __syncthreads();                      // single barrier per chunk

        uint32_t stg = sb + buf * STAGE;
        #pragma unroll
        for (int kk = 0; kk < 2; ++kk) {
            uint32_t a_h[2][4], a_l[2][4];
            #pragma unroll
            for (int mt = 0; mt < 2; ++mt) {
                uint32_t ra = stg + AHo + (wy*32 + mt*16 + arow) * RS + kk*32 + acolb;
                LDSM4(a_h[mt], ra);
                LDSM4(a_l[mt], ra + (ALo - AHo));
            }
            uint32_t b_h[2][4], b_l[2][4];
            #pragma unroll
            for (int p = 0; p < 2; ++p) {
                uint32_t rb = stg + BHo + (wx*32 + p*16 + nrow) * RS + kk*32 + bcolb;
                LDSM4(b_h[p], rb);
                LDSM4(b_l[p], rb + BSZ);
            }
            #pragma unroll
            for (int mt = 0; mt < 2; ++mt)
                #pragma unroll
                for (int p = 0; p < 2; ++p)
                    #pragma unroll
                    for (int h = 0; h < 2; ++h) {
                        float* d = accE[mt][p*2 + h];
                        MMA16816(d, a_h[mt], b_h[p][h*2], b_h[p][h*2+1]);
                        MMA16816(d, a_h[mt], b_l[p][h*2], b_l[p][h*2+1]);
                        MMA16816(d, a_l[mt], b_h[p][h*2], b_h[p][h*2+1]);
                    }
        }

        // issue loads for chunk c+2 into the stage retired at chunk c-1
        if (c + 2 < nc) {
            int nb = buf + 2; if (nb >= 3) nb -= 3;
            load_chunk(c + 2, nb);
        }

        // expert boundary: fold w[b,e]*inv into output accumulator
        if (((c + 1) & (CPE - 1)) == 0) {
            int e = e0 + c / CPE;
            float wv0[2], wv1[2];
            #pragma unroll
            for (int mt = 0; mt < 2; ++mt) {
                int r = m0 + wy*32 + mt*16 + g;
                wv0[mt] = w[(size_t)r * NE + e] * inv;
                wv1[mt] = w[(size_t)(r + 8) * NE + e] * inv;
            }
            #pragma unroll
            for (int mt = 0; mt < 2; ++mt)
                #pragma unroll
                for (int nt = 0; nt < 4; ++nt) {
                    accO[mt][nt][0] = fmaf(wv0[mt], accE[mt][nt][0], accO[mt][nt][0]);
                    accO[mt][nt][1] = fmaf(wv0[mt], accE[mt][nt][1], accO[mt][nt][1]);
                    accO[mt][nt][2] = fmaf(wv1[mt], accE[mt][nt][2], accO[mt][nt][2]);
                    accO[mt][nt][3] = fmaf(wv1[mt], accE[mt][nt][3], accO[mt][nt][3]);
                    accE[mt][nt][0] = 0.f; accE[mt][nt][1] = 0.f;
                    accE[mt][nt][2] = 0.f; accE[mt][nt][3] = 0.f;
                }
        }

        if (++buf >= 3) buf -= 3;
    }

    // ---- epilogue: atomicAdd into bias-initialized out ----
    #pragma unroll
    for (int mt = 0; mt < 2; ++mt)
        #pragma unroll
        for (int nt = 0; nt < 4; ++nt) {
            int row = m0 + wy*32 + mt*16 + g;
            int col = n0 + wx*32 + nt*8 + tig*2;
            float* p0 = out + (size_t)row * O + col;
            atomicAdd(p0,     accO[mt][nt][0]);
            atomicAdd(p0 + 1, accO[mt][nt][1]);
            float* p1 = p0 + (size_t)8 * O;
            atomicAdd(p1,     accO[mt][nt][2]);
            atomicAdd(p1 + 1, accO[mt][nt][3]);
        }
}

// ===========================================================================
extern "C" void kernel_launch(void* const* d_in, const int* in_sizes, int n_in,
                              void* d_out, int out_size) {
    const float* m0    = (const float*)d_in[0];
    const float* x0    = (const float*)d_in[1];
    const float* mW1   = (const float*)d_in[2];
    const float* mb1   = (const float*)d_in[3];
    const float* mg1   = (const float*)d_in[4];
    const float* mbe1  = (const float*)d_in[5];
    const float* ma1   = (const float*)d_in[6];
    const float* mW2   = (const float*)d_in[7];
    const float* mb2   = (const float*)d_in[8];
    const float* mg2   = (const float*)d_in[9];
    const float* mbe2  = (const float*)d_in[10];
    const float* ma2   = (const float*)d_in[11];
    const float* mW3   = (const float*)d_in[12];
    const float* mb3   = (const float*)d_in[13];
    const float* mg3   = (const float*)d_in[14];
    const float* mbe3  = (const float*)d_in[15];
    const float* ma3   = (const float*)d_in[16];
    const float* Wenc0 = (const float*)d_in[17];
    const float* benc0 = (const float*)d_in[18];
    const float* Wenc1 = (const float*)d_in[19];
    const float* benc1 = (const float*)d_in[20];
    const float* Wdec0 = (const float*)d_in[21];
    const float* bdec0 = (const float*)d_in[22];
    const float* Wdec1 = (const float*)d_in[23];
    const float* bdec1 = (const float*)d_in[24];
    const float* bng   = (const float*)d_in[25];
    const float* bnb   = (const float*)d_in[26];
    const float* aP    = (const float*)d_in[27];
    float* out = (float*)d_out;

    float *b0, *b1, *b2, *wb;
    __nv_bfloat16 *Wh, *Wl, *Zh, *Zl;
    cudaGetSymbolAddress((void**)&b0, g_buf0);
    cudaGetSymbolAddress((void**)&b1, g_buf1);
    cudaGetSymbolAddress((void**)&b2, g_buf2);
    cudaGetSymbolAddress((void**)&wb, g_w);
    cudaGetSymbolAddress((void**)&Wh, g_Wh);
    cudaGetSymbolAddress((void**)&Wl, g_Wl);
    cudaGetSymbolAddress((void**)&Zh, g_Zh);
    cudaGetSymbolAddress((void**)&Zl, g_Zl);

    const int SMEM = 92160;   // 3 stages x 30720
    cudaFuncSetAttribute(expert_mma_kernel<64>,
                         cudaFuncAttributeMaxDynamicSharedMemorySize, SMEM);
    cudaFuncSetAttribute(expert_mma_kernel<256>,
                         cudaFuncAttributeMaxDynamicSharedMemorySize, SMEM);

    // ---- pre-split expert weights to bf16 hi/lo ----
    split_w_kernel<<< 512, 256>>>(Wenc0, Wh + OFF_ENC0, Wl + OFF_ENC0, 1048576 / 8);
    split_w_kernel<<<2048, 256>>>(Wenc1, Wh + OFF_ENC1, Wl + OFF_ENC1, 4194304 / 8);
    split_w_kernel<<<2048, 256>>>(Wdec0, Wh + OFF_DEC0, Wl + OFF_DEC0, 4194304 / 8);
    split_w_kernel<<< 512, 256>>>(Wdec1, Wh + OFF_DEC1, Wl + OFF_DEC1, 1048576 / 8);

    // ---- MNet: 3x (Linear -> BN -> PReLU) -> w [4096,64] ----
    gemm_bias_kernel<<<dim3(4, 64), 256>>>(m0, mW1, mb1, b0, 128, 256);
    bn_prelu_kernel<<<128, 256>>>(b0, mg1, mbe1, ma1, 256);
    gemm_bias_kernel<<<dim3(2, 64), 256>>>(b0, mW2, mb2, b1, 256, 128);
    bn_prelu_kernel<<<64, 256>>>(b1, mg2, mbe2, ma2, 128);
    gemm_bias_kernel<<<dim3(1, 64), 256>>>(b1, mW3, mb3, wb, 128, 64);
    bn_prelu_kernel<<<32, 256>>>(wb, mg3, mbe3, ma3, 64);

    zero_sum_kernel<<<1, 1>>>();
    reduce_w_kernel<<<64, 256>>>(wb);
    inv_kernel<<<1, 1>>>();

    // ---- encoder layer 0: x0[4096,64] -> b2[4096,256] ----
    split_w_kernel<<<128, 256>>>(x0, Zh, Zl, BATCH * 64 / 8);
    bias_combine_kernel<<<BATCH * 256 / 256, 256>>>(wb, benc0, b2, 256);
    expert_mma_kernel<64><<<dim3(4, 32, 2), 256, SMEM>>>(
        Zh, Zl, Wh + OFF_ENC0, Wl + OFF_ENC0, wb, b2, 256, 32);
    bn_prelu_split_kernel<<<128, 256>>>(b2, bng, bnb, aP, 256, Zh, Zl);

    // ---- encoder layer 1: -> b0 ----
    bias_combine_kernel<<<BATCH * 256 / 256, 256>>>(wb, benc1, b0, 256);
    expert_mma_kernel<256><<<dim3(4, 32, 4), 256, SMEM>>>(
        Zh, Zl, Wh + OFF_ENC1, Wl + OFF_ENC1, wb, b0, 256, 16);
    bn_prelu_split_kernel<<<128, 256>>>(b0, bng, bnb, aP, 256, Zh, Zl);

    // ---- decoder layer 0: -> b1 ----
    bias_combine_kernel<<<BATCH * 256 / 256, 256>>>(wb, bdec0, b1, 256);
    expert_mma_kernel<256><<<dim3(4, 32, 4), 256, SMEM>>>(
        Zh, Zl, Wh + OFF_DEC0, Wl + OFF_DEC0, wb, b1, 256, 16);
    bn_prelu_split_kernel<<<128, 256>>>(b1, bng, bnb, aP, 256, Zh, Zl);

    // ---- decoder layer 1 (no BN/PReLU): -> out [4096,64] ----
    bias_combine_kernel<<<BATCH * 64 / 256, 256>>>(wb, bdec1, out, 64);
    expert_mma_kernel<256><<<dim3(1, 32, 8), 256, SMEM>>>(
        Zh, Zl, Wh + OFF_DEC1, Wl + OFF_DEC1, wb, out, 64, 8);
}

// round 7
// speedup vs baseline: 2.7854x; 1.0974x over previous
#include <cuda_runtime.h>
#include <cuda_bf16.h>
#include <cstdint>

#define BATCH 4096
#define NE    64
#define EPSV  1e-5f

// ===================== device scratch (no runtime alloc) ====================
__device__ __align__(16) float g_buf0[BATCH * 256];
__device__ __align__(16) float g_buf1[BATCH * 256];
__device__ __align__(16) float g_buf2[BATCH * 256];
__device__ __align__(16) float g_w   [BATCH * NE];
__device__ float g_sum;

// activation bf16 hi/lo (max 4096 x 256)
__device__ __align__(16) __nv_bfloat16 g_Zh[BATCH * 256];
__device__ __align__(16) __nv_bfloat16 g_Zl[BATCH * 256];

// split-bf16 weights: enc0(1M) enc1(4M) dec0(4M) dec1(1M) = 10.5M elems
#define OFF_ENC0 0
#define OFF_ENC1 1048576
#define OFF_DEC0 5242880
#define OFF_DEC1 9437184
#define W_TOTAL  10485760
__device__ __align__(16) __nv_bfloat16 g_Wh[W_TOTAL];
__device__ __align__(16) __nv_bfloat16 g_Wl[W_TOTAL];

// ===================== PTX helpers (base sm_103 target only) ===============
__device__ __forceinline__ uint32_t smem_u32(const void* p) {
    uint32_t a;
    asm("{ .reg .u64 t; cvta.to.shared.u64 t, %1; cvt.u32.u64 %0, t; }"
        : "=r"(a) : "l"(p));
    return a;
}

#define LDSM4(r, a) \
    asm volatile("ldmatrix.sync.aligned.m8n8.x4.shared.b16 {%0,%1,%2,%3}, [%4];" \
        : "=r"((r)[0]), "=r"((r)[1]), "=r"((r)[2]), "=r"((r)[3]) : "r"(a))

#define MMA16816(d, a, b0v, b1v) \
    asm volatile("mma.sync.aligned.m16n8k16.row.col.f32.bf16.bf16.f32 " \
        "{%0,%1,%2,%3}, {%4,%5,%6,%7}, {%8,%9}, {%0,%1,%2,%3};" \
        : "+f"((d)[0]), "+f"((d)[1]), "+f"((d)[2]), "+f"((d)[3]) \
        : "r"((a)[0]), "r"((a)[1]), "r"((a)[2]), "r"((a)[3]), "r"(b0v), "r"(b1v))

#define CP_ASYNC16(dst, src) \
    asm volatile("cp.async.cg.shared.global [%0], [%1], 16;" :: "r"(dst), "l"(src))
#define CP_COMMIT() asm volatile("cp.async.commit_group;" ::: "memory")
#define CP_WAIT1()  asm volatile("cp.async.wait_group 1;" ::: "memory")
#define CP_WAIT0()  asm volatile("cp.async.wait_group 0;" ::: "memory")

// ============ split fp32 -> bf16 hi/lo helper (8 elems per thread) =========
__device__ __forceinline__ void split8(const float* __restrict__ src8,
                                       uint4& hv, uint4& lv) {
    float4 v0 = reinterpret_cast<const float4*>(src8)[0];
    float4 v1 = reinterpret_cast<const float4*>(src8)[1];
    float f[8] = {v0.x, v0.y, v0.z, v0.w, v1.x, v1.y, v1.z, v1.w};
    uint32_t hw[4], lw[4];
    #pragma unroll
    for (int j = 0; j < 4; ++j) {
        __nv_bfloat162 h2 = __floats2bfloat162_rn(f[2*j], f[2*j+1]);
        float q0 = f[2*j]   - __low2float(h2);
        float q1 = f[2*j+1] - __high2float(h2);
        __nv_bfloat162 l2 = __floats2bfloat162_rn(q0, q1);
        hw[j] = *reinterpret_cast<uint32_t*>(&h2);
        lw[j] = *reinterpret_cast<uint32_t*>(&l2);
    }
    hv = make_uint4(hw[0], hw[1], hw[2], hw[3]);
    lv = make_uint4(lw[0], lw[1], lw[2], lw[3]);
}

// ---- all 4 expert-weight tensors split in ONE kernel ----
__global__ __launch_bounds__(256)
void split_all_kernel(const float* __restrict__ W0, const float* __restrict__ W1,
                      const float* __restrict__ W2, const float* __restrict__ W3,
                      __nv_bfloat16* __restrict__ Wh, __nv_bfloat16* __restrict__ Wl) {
    int i = blockIdx.x * 256 + threadIdx.x;    // i over W_TOTAL/8
    const float* src; int base;
    if      (i < OFF_ENC1 / 8) { src = W0; base = 0; }
    else if (i < OFF_DEC0 / 8) { src = W1; base = OFF_ENC1 / 8; }
    else if (i < OFF_DEC1 / 8) { src = W2; base = OFF_DEC0 / 8; }
    else                       { src = W3; base = OFF_DEC1 / 8; }
    uint4 hv, lv;
    split8(src + (size_t)(i - base) * 8, hv, lv);
    reinterpret_cast<uint4*>(Wh)[i] = hv;
    reinterpret_cast<uint4*>(Wl)[i] = lv;
}

// ---- generic single-tensor split (x0) ----
__global__ __launch_bounds__(256)
void split_w_kernel(const float* __restrict__ W, __nv_bfloat16* __restrict__ Wh,
                    __nv_bfloat16* __restrict__ Wl, int n8) {
    int i = blockIdx.x * 256 + threadIdx.x;
    if (i >= n8) return;
    uint4 hv, lv;
    split8(W + (size_t)i * 8, hv, lv);
    reinterpret_cast<uint4*>(Wh)[i] = hv;
    reinterpret_cast<uint4*>(Wl)[i] = lv;
}

// ===================== small GEMM (MNet, fp32 SIMT) ========================
__global__ __launch_bounds__(256)
void gemm_bias_kernel(const float* __restrict__ X, const float* __restrict__ W,
                      const float* __restrict__ bias, float* __restrict__ C,
                      int K, int N) {
    const int BM = 64, BN = 64, BK = 16, TM = 4, TN = 4;
    __shared__ __align__(16) float As[BK][BM];
    __shared__ __align__(16) float Bs[BK][BN];
    int tid  = threadIdx.x;
    int n0   = blockIdx.x * BN;
    int m0   = blockIdx.y * BM;
    int tn   = tid & 15, tm = tid >> 4;
    int row0 = tm * TM, col0 = tn * TN;
    int lr   = tid >> 2, ls = tid & 3;
    float acc[TM][TN] = {};
    for (int k0 = 0; k0 < K; k0 += BK) {
        float4 av = *reinterpret_cast<const float4*>(&X[(size_t)(m0 + lr) * K + k0 + ls * 4]);
        As[ls*4+0][lr] = av.x; As[ls*4+1][lr] = av.y; As[ls*4+2][lr] = av.z; As[ls*4+3][lr] = av.w;
        float4 bv = *reinterpret_cast<const float4*>(&W[(size_t)(n0 + lr) * K + k0 + ls * 4]);
        Bs[ls*4+0][lr] = bv.x; Bs[ls*4+1][lr] = bv.y; Bs[ls*4+2][lr] = bv.z; Bs[ls*4+3][lr] = bv.w;
        __syncthreads();
        #pragma unroll
        for (int kk = 0; kk < BK; ++kk) {
            float a[TM], b[TN];
            float4 va = *reinterpret_cast<const float4*>(&As[kk][row0]);
            a[0]=va.x; a[1]=va.y; a[2]=va.z; a[3]=va.w;
            float4 vb = *reinterpret_cast<const float4*>(&Bs[kk][col0]);
            b[0]=vb.x; b[1]=vb.y; b[2]=vb.z; b[3]=vb.w;
            #pragma unroll
            for (int i = 0; i < TM; i++)
                #pragma unroll
                for (int j = 0; j < TN; j++)
                    acc[i][j] = fmaf(a[i], b[j], acc[i][j]);
        }
        __syncthreads();
    }
    #pragma unroll
    for (int i = 0; i < TM; i++)
        #pragma unroll
        for (int j = 0; j < TN; j++)
            C[(size_t)(m0 + row0 + i) * N + n0 + col0 + j] = acc[i][j] + bias[n0 + col0 + j];
}

// ============ BN + PReLU in place (MNet path, fp32 out) ====================
__global__ __launch_bounds__(256)
void bn_prelu_kernel(float* __restrict__ X, const float* __restrict__ g,
                     const float* __restrict__ be, const float* __restrict__ aP,
                     int C) {
    __shared__ float s1[256], s2[256];
    int tid = threadIdx.x;
    int col = blockIdx.x * 2 + (tid & 1);
    int r0  = tid >> 1;
    float sum = 0.f, sq = 0.f;
    for (int r = r0; r < BATCH; r += 128) {
        float v = X[(size_t)r * C + col];
        sum += v; sq += v * v;
    }
    s1[tid] = sum; s2[tid] = sq;
    __syncthreads();
    #pragma unroll
    for (int off = 128; off >= 2; off >>= 1) {
        if (tid < off) { s1[tid] += s1[tid + off]; s2[tid] += s2[tid + off]; }
        __syncthreads();
    }
    float mean = s1[tid & 1] * (1.f / BATCH);
    float var  = s2[tid & 1] * (1.f / BATCH) - mean * mean;
    float sc   = g[col] * rsqrtf(var + EPSV);
    float sh   = be[col] - mean * sc;
    float a    = aP[0];
    for (int r = r0; r < BATCH; r += 128) {
        float v = X[(size_t)r * C + col] * sc + sh;
        X[(size_t)r * C + col] = (v >= 0.f) ? v : a * v;
    }
}

// ====== BN + PReLU fused with bf16 hi/lo split (expert path) ===============
__global__ __launch_bounds__(256)
void bn_prelu_split_kernel(const float* __restrict__ X, const float* __restrict__ g,
                           const float* __restrict__ be, const float* __restrict__ aP,
                           int C, __nv_bfloat16* __restrict__ Zh,
                           __nv_bfloat16* __restrict__ Zl) {
    __shared__ float s1[256], s2[256];
    int tid = threadIdx.x;
    int col = blockIdx.x * 2 + (tid & 1);
    int r0  = tid >> 1;
    float sum = 0.f, sq = 0.f;
    for (int r = r0; r < BATCH; r += 128) {
        float v = X[(size_t)r * C + col];
        sum += v; sq += v * v;
    }
    s1[tid] = sum; s2[tid] = sq;
    __syncthreads();
    #pragma unroll
    for (int off = 128; off >= 2; off >>= 1) {
        if (tid < off) { s1[tid] += s1[tid + off]; s2[tid] += s2[tid + off]; }
        __syncthreads();
    }
    float mean = s1[tid & 1] * (1.f / BATCH);
    float var  = s2[tid & 1] * (1.f / BATCH) - mean * mean;
    float sc   = g[col] * rsqrtf(var + EPSV);
    float sh   = be[col] - mean * sc;
    float a    = aP[0];
    for (int r = r0; r < BATCH; r += 128) {
        float v = X[(size_t)r * C + col] * sc + sh;
        v = (v >= 0.f) ? v : a * v;
        __nv_bfloat16 h = __float2bfloat16_rn(v);
        __nv_bfloat16 l = __float2bfloat16_rn(v - __bfloat162float(h));
        Zh[(size_t)r * C + col] = h;
        Zl[(size_t)r * C + col] = l;
    }
}

// =========== single-block global sum (writes g_sum directly) ===============
__global__ __launch_bounds__(1024)
void reduce_w_kernel(const float* __restrict__ w) {
    __shared__ float s[1024];
    int tid = threadIdx.x;
    float a = 0.f;
    const float4* w4 = reinterpret_cast<const float4*>(w);
    for (int i = tid; i < BATCH * NE / 4; i += 1024) {
        float4 v = w4[i];
        a += (v.x + v.y) + (v.z + v.w);
    }
    s[tid] = a; __syncthreads();
    #pragma unroll
    for (int off = 512; off; off >>= 1) {
        if (tid < off) s[tid] += s[tid + off];
        __syncthreads();
    }
    if (tid == 0) g_sum = s[0];
}

// ===================== mma.sync expert GEMM (split-bf16) ===================
// accO[b,o] = sum_e (w[b,e]*inv) * (z[b,:] . W[e,o,:] + bias[e,o])
// 3-stage cp.async ring, ONE __syncthreads per chunk; bias folded into accE
// init; out must be zero-initialized (memset); split-K over experts.
template<int IDIM>
__global__ __launch_bounds__(256, 2)
void expert_mma_kernel(const __nv_bfloat16* __restrict__ Zh,
                       const __nv_bfloat16* __restrict__ Zl,
                       const __nv_bfloat16* __restrict__ Wh,
                       const __nv_bfloat16* __restrict__ Wl,
                       const float* __restrict__ w,
                       const float* __restrict__ bias,
                       float* __restrict__ out,
                       int O, int eper) {
    constexpr int RS    = 80;                 // padded row stride (bytes)
    constexpr int AHo   = 0;
    constexpr int ALo   = 128 * RS;           // 10240
    constexpr int BHo   = 2 * 128 * RS;       // 20480
    constexpr int BSZ   = 64 * RS;            // 5120
    constexpr int STAGE = BHo + 2 * BSZ;      // 30720
    constexpr int CPE   = IDIM / 32;          // chunks per expert

    extern __shared__ char smem[];
    uint32_t sb = smem_u32(smem);

    int tid  = threadIdx.x;
    int lane = tid & 31, wid = tid >> 5;
    int wy = wid >> 1, wx = wid & 1;          // 4 M-warps x 2 N-warps
    int m0 = blockIdx.y * 128;
    int n0 = blockIdx.x * 64;
    int e0 = blockIdx.z * eper;
    float inv = 1.f / g_sum;
    const int nc = eper * CPE;

    auto load_chunk = [&](int c, int buf) {
        int e  = e0 + c / CPE;
        int i0 = (c % CPE) * 32;
        uint32_t stg = sb + buf * STAGE;
        #pragma unroll
        for (int it = 0; it < 4; ++it) {
            int idx  = tid + it * 256;
            int half = idx >> 9;
            int rsd  = idx & 511;
            int row  = rsd >> 2, ch = rsd & 3;
            const __nv_bfloat16* src =
                (half ? Zl : Zh) + (size_t)(m0 + row) * IDIM + i0 + ch * 8;
            CP_ASYNC16(stg + half * (ALo - AHo) + row * RS + ch * 16, src);
        }
        #pragma unroll
        for (int it = 0; it < 2; ++it) {
            int idx  = tid + it * 256;
            int half = idx >> 8;
            int rsd  = idx & 255;
            int row  = rsd >> 2, ch = rsd & 3;
            const __nv_bfloat16* src =
                (half ? Wl : Wh) + ((size_t)e * O + n0 + row) * IDIM + i0 + ch * 8;
            CP_ASYNC16(stg + BHo + half * BSZ + row * RS + ch * 16, src);
        }
        CP_COMMIT();
    };

    float accE[2][4][4];
    float accO[2][4][4] = {};
    int g   = lane >> 2;
    int tig = lane & 3;

    // bias init helper: accE <- bias[e, col] (cols depend on nt only)
    auto set_bias = [&](int e) {
        #pragma unroll
        for (int nt = 0; nt < 4; ++nt) {
            int col = n0 + wx*32 + nt*8 + tig*2;
            float2 bv = *reinterpret_cast<const float2*>(&bias[(size_t)e * O + col]);
            #pragma unroll
            for (int mt = 0; mt < 2; ++mt) {
                accE[mt][nt][0] = bv.x; accE[mt][nt][1] = bv.y;
                accE[mt][nt][2] = bv.x; accE[mt][nt][3] = bv.y;
            }
        }
    };
    set_bias(e0);

    // ldmatrix address constants
    int arow  = lane & 15;
    int acolb = (lane >> 4) * 16;
    int nrow  = (lane & 7) + ((lane >> 4) << 3);
    int bcolb = ((lane >> 3) & 1) * 16;

    // prologue: fill 2 of 3 stages
    load_chunk(0, 0);
    load_chunk(1, 1);

    int buf = 0;
    for (int c = 0; c < nc; ++c) {
        if (c + 1 < nc) CP_WAIT1(); else CP_WAIT0();
        __syncthreads();                      // single barrier per chunk

        uint32_t stg = sb + buf * STAGE;
        #pragma unroll
        for (int kk = 0; kk < 2; ++kk) {
            uint32_t a_h[2][4], a_l[2][4];
            #pragma unroll
            for (int mt = 0; mt < 2; ++mt) {
                uint32_t ra = stg + AHo + (wy*32 + mt*16 + arow) * RS + kk*32 + acolb;
                LDSM4(a_h[mt], ra);
                LDSM4(a_l[mt], ra + (ALo - AHo));
            }
            uint32_t b_h[2][4], b_l[2][4];
            #pragma unroll
            for (int p = 0; p < 2; ++p) {
                uint32_t rb = stg + BHo + (wx*32 + p*16 + nrow) * RS + kk*32 + bcolb;
                LDSM4(b_h[p], rb);
                LDSM4(b_l[p], rb + BSZ);
            }
            #pragma unroll
            for (int mt = 0; mt < 2; ++mt)
                #pragma unroll
                for (int p = 0; p < 2; ++p)
                    #pragma unroll
                    for (int h = 0; h < 2; ++h) {
                        float* d = accE[mt][p*2 + h];
                        MMA16816(d, a_h[mt], b_h[p][h*2], b_h[p][h*2+1]);
                        MMA16816(d, a_h[mt], b_l[p][h*2], b_l[p][h*2+1]);
                        MMA16816(d, a_l[mt], b_h[p][h*2], b_h[p][h*2+1]);
                    }
        }

        // issue loads for chunk c+2 into the stage retired at chunk c-1
        if (c + 2 < nc) {
            int nb = buf + 2; if (nb >= 3) nb -= 3;
            load_chunk(c + 2, nb);
        }

        // expert boundary: fold w[b,e]*inv into output accumulator
        if (((c + 1) & (CPE - 1)) == 0) {
            int e = e0 + c / CPE;
            float wv0[2], wv1[2];
            #pragma unroll
            for (int mt = 0; mt < 2; ++mt) {
                int r = m0 + wy*32 + mt*16 + g;
                wv0[mt] = w[(size_t)r * NE + e] * inv;
                wv1[mt] = w[(size_t)(r + 8) * NE + e] * inv;
            }
            #pragma unroll
            for (int mt = 0; mt < 2; ++mt)
                #pragma unroll
                for (int nt = 0; nt < 4; ++nt) {
                    accO[mt][nt][0] = fmaf(wv0[mt], accE[mt][nt][0], accO[mt][nt][0]);
                    accO[mt][nt][1] = fmaf(wv0[mt], accE[mt][nt][1], accO[mt][nt][1]);
                    accO[mt][nt][2] = fmaf(wv1[mt], accE[mt][nt][2], accO[mt][nt][2]);
                    accO[mt][nt][3] = fmaf(wv1[mt], accE[mt][nt][3], accO[mt][nt][3]);
                }
            if (c + 1 < nc) set_bias(e + 1);
        }

        if (++buf >= 3) buf -= 3;
    }

    // ---- epilogue: atomicAdd into zero-initialized out ----
    #pragma unroll
    for (int mt = 0; mt < 2; ++mt)
        #pragma unroll
        for (int nt = 0; nt < 4; ++nt) {
            int row = m0 + wy*32 + mt*16 + g;
            int col = n0 + wx*32 + nt*8 + tig*2;
            float* p0 = out + (size_t)row * O + col;
            atomicAdd(p0,     accO[mt][nt][0]);
            atomicAdd(p0 + 1, accO[mt][nt][1]);
            float* p1 = p0 + (size_t)8 * O;
            atomicAdd(p1,     accO[mt][nt][2]);
            atomicAdd(p1 + 1, accO[mt][nt][3]);
        }
}

// ===========================================================================
extern "C" void kernel_launch(void* const* d_in, const int* in_sizes, int n_in,
                              void* d_out, int out_size) {
    const float* m0    = (const float*)d_in[0];
    const float* x0    = (const float*)d_in[1];
    const float* mW1   = (const float*)d_in[2];
    const float* mb1   = (const float*)d_in[3];
    const float* mg1   = (const float*)d_in[4];
    const float* mbe1  = (const float*)d_in[5];
    const float* ma1   = (const float*)d_in[6];
    const float* mW2   = (const float*)d_in[7];
    const float* mb2   = (const float*)d_in[8];
    const float* mg2   = (const float*)d_in[9];
    const float* mbe2  = (const float*)d_in[10];
    const float* ma2   = (const float*)d_in[11];
    const float* mW3   = (const float*)d_in[12];
    const float* mb3   = (const float*)d_in[13];
    const float* mg3   = (const float*)d_in[14];
    const float* mbe3  = (const float*)d_in[15];
    const float* ma3   = (const float*)d_in[16];
    const float* Wenc0 = (const float*)d_in[17];
    const float* benc0 = (const float*)d_in[18];
    const float* Wenc1 = (const float*)d_in[19];
    const float* benc1 = (const float*)d_in[20];
    const float* Wdec0 = (const float*)d_in[21];
    const float* bdec0 = (const float*)d_in[22];
    const float* Wdec1 = (const float*)d_in[23];
    const float* bdec1 = (const float*)d_in[24];
    const float* bng   = (const float*)d_in[25];
    const float* bnb   = (const float*)d_in[26];
    const float* aP    = (const float*)d_in[27];
    float* out = (float*)d_out;

    float *b0, *b1, *b2, *wb;
    __nv_bfloat16 *Wh, *Wl, *Zh, *Zl;
    cudaGetSymbolAddress((void**)&b0, g_buf0);
    cudaGetSymbolAddress((void**)&b1, g_buf1);
    cudaGetSymbolAddress((void**)&b2, g_buf2);
    cudaGetSymbolAddress((void**)&wb, g_w);
    cudaGetSymbolAddress((void**)&Wh, g_Wh);
    cudaGetSymbolAddress((void**)&Wl, g_Wl);
    cudaGetSymbolAddress((void**)&Zh, g_Zh);
    cudaGetSymbolAddress((void**)&Zl, g_Zl);

    const int SMEM = 92160;   // 3 stages x 30720
    cudaFuncSetAttribute(expert_mma_kernel<64>,
                         cudaFuncAttributeMaxDynamicSharedMemorySize, SMEM);
    cudaFuncSetAttribute(expert_mma_kernel<256>,
                         cudaFuncAttributeMaxDynamicSharedMemorySize, SMEM);

    // ---- pre-split all expert weights (one kernel) ----
    split_all_kernel<<<W_TOTAL / 8 / 256, 256>>>(Wenc0, Wenc1, Wdec0, Wdec1, Wh, Wl);

    // ---- MNet: 3x (Linear -> BN -> PReLU) -> w [4096,64] ----
    gemm_bias_kernel<<<dim3(4, 64), 256>>>(m0, mW1, mb1, b0, 128, 256);
    bn_prelu_kernel<<<128, 256>>>(b0, mg1, mbe1, ma1, 256);
    gemm_bias_kernel<<<dim3(2, 64), 256>>>(b0, mW2, mb2, b1, 256, 128);
    bn_prelu_kernel<<<64, 256>>>(b1, mg2, mbe2, ma2, 128);
    gemm_bias_kernel<<<dim3(1, 64), 256>>>(b1, mW3, mb3, wb, 128, 64);
    bn_prelu_kernel<<<32, 256>>>(wb, mg3, mbe3, ma3, 64);
    reduce_w_kernel<<<1, 1024>>>(wb);

    // ---- encoder layer 0: x0[4096,64] -> b2[4096,256] ----
    split_w_kernel<<<128, 256>>>(x0, Zh, Zl, BATCH * 64 / 8);
    cudaMemsetAsync(b2, 0, BATCH * 256 * sizeof(float));
    expert_mma_kernel<64><<<dim3(4, 32, 2), 256, SMEM>>>(
        Zh, Zl, Wh + OFF_ENC0, Wl + OFF_ENC0, wb, benc0, b2, 256, 32);
    bn_prelu_split_kernel<<<128, 256>>>(b2, bng, bnb, aP, 256, Zh, Zl);

    // ---- encoder layer 1: -> b0 ----
    cudaMemsetAsync(b0, 0, BATCH * 256 * sizeof(float));
    expert_mma_kernel<256><<<dim3(4, 32, 4), 256, SMEM>>>(
        Zh, Zl, Wh + OFF_ENC1, Wl + OFF_ENC1, wb, benc1, b0, 256, 16);
    bn_prelu_split_kernel<<<128, 256>>>(b0, bng, bnb, aP, 256, Zh, Zl);

    // ---- decoder layer 0: -> b1 ----
    cudaMemsetAsync(b1, 0, BATCH * 256 * sizeof(float));
    expert_mma_kernel<256><<<dim3(4, 32, 4), 256, SMEM>>>(
        Zh, Zl, Wh + OFF_DEC0, Wl + OFF_DEC0, wb, bdec0, b1, 256, 16);
    bn_prelu_split_kernel<<<128, 256>>>(b1, bng, bnb, aP, 256, Zh, Zl);

    // ---- decoder layer 1 (no BN/PReLU): -> out [4096,64] ----
    cudaMemsetAsync(out, 0, BATCH * 64 * sizeof(float));
    expert_mma_kernel<256><<<dim3(1, 32, 8), 256, SMEM>>>(
        Zh, Zl, Wh + OFF_DEC1, Wl + OFF_DEC1, wb, bdec1, out, 64, 8);
}

// round 8
// speedup vs baseline: 4.7868x; 1.7185x over previous
#include <cuda_runtime.h>
#include <cuda_fp16.h>
#include <cstdint>

#define BATCH 4096
#define NE    64
#define EPSV  1e-5f

// ===================== device scratch (no runtime alloc) ====================
__device__ __align__(16) float g_buf0[BATCH * 256];
__device__ __align__(16) float g_buf1[BATCH * 256];
__device__ __align__(16) float g_buf2[BATCH * 256];
__device__ __align__(16) float g_w   [BATCH * NE];
__device__ float g_sum;

// activation fp16 (max 4096 x 256)
__device__ __align__(16) __half g_Zf[BATCH * 256];

// fp16 weights: enc0(1M) enc1(4M) dec0(4M) dec1(1M) = 10.5M elems
#define OFF_ENC0 0
#define OFF_ENC1 1048576
#define OFF_DEC0 5242880
#define OFF_DEC1 9437184
#define W_TOTAL  10485760
__device__ __align__(16) __half g_Wf[W_TOTAL];

// ===================== PTX helpers (base sm_103 target only) ===============
__device__ __forceinline__ uint32_t smem_u32(const void* p) {
    uint32_t a;
    asm("{ .reg .u64 t; cvta.to.shared.u64 t, %1; cvt.u32.u64 %0, t; }"
        : "=r"(a) : "l"(p));
    return a;
}

#define LDSM4(r, a) \
    asm volatile("ldmatrix.sync.aligned.m8n8.x4.shared.b16 {%0,%1,%2,%3}, [%4];" \
        : "=r"((r)[0]), "=r"((r)[1]), "=r"((r)[2]), "=r"((r)[3]) : "r"(a))

#define MMA16816H(d, a, b0v, b1v) \
    asm volatile("mma.sync.aligned.m16n8k16.row.col.f32.f16.f16.f32 " \
        "{%0,%1,%2,%3}, {%4,%5,%6,%7}, {%8,%9}, {%0,%1,%2,%3};" \
        : "+f"((d)[0]), "+f"((d)[1]), "+f"((d)[2]), "+f"((d)[3]) \
        : "r"((a)[0]), "r"((a)[1]), "r"((a)[2]), "r"((a)[3]), "r"(b0v), "r"(b1v))

#define CP_ASYNC16(dst, src) \
    asm volatile("cp.async.cg.shared.global [%0], [%1], 16;" :: "r"(dst), "l"(src))
#define CP_COMMIT() asm volatile("cp.async.commit_group;" ::: "memory")
#define CP_WAIT1()  asm volatile("cp.async.wait_group 1;" ::: "memory")
#define CP_WAIT0()  asm volatile("cp.async.wait_group 0;" ::: "memory")

// ============ convert fp32 -> fp16 (8 elems per thread) ====================
__device__ __forceinline__ uint4 cvt8(const float* __restrict__ src8) {
    float4 v0 = reinterpret_cast<const float4*>(src8)[0];
    float4 v1 = reinterpret_cast<const float4*>(src8)[1];
    __half2 h0 = __floats2half2_rn(v0.x, v0.y);
    __half2 h1 = __floats2half2_rn(v0.z, v0.w);
    __half2 h2 = __floats2half2_rn(v1.x, v1.y);
    __half2 h3 = __floats2half2_rn(v1.z, v1.w);
    return make_uint4(*reinterpret_cast<uint32_t*>(&h0),
                      *reinterpret_cast<uint32_t*>(&h1),
                      *reinterpret_cast<uint32_t*>(&h2),
                      *reinterpret_cast<uint32_t*>(&h3));
}

// ---- all 4 expert-weight tensors converted in ONE kernel ----
__global__ __launch_bounds__(256)
void cvt_all_kernel(const float* __restrict__ W0, const float* __restrict__ W1,
                    const float* __restrict__ W2, const float* __restrict__ W3,
                    __half* __restrict__ Wf) {
    int i = blockIdx.x * 256 + threadIdx.x;    // i over W_TOTAL/8
    const float* src; int base;
    if      (i < OFF_ENC1 / 8) { src = W0; base = 0; }
    else if (i < OFF_DEC0 / 8) { src = W1; base = OFF_ENC1 / 8; }
    else if (i < OFF_DEC1 / 8) { src = W2; base = OFF_DEC0 / 8; }
    else                       { src = W3; base = OFF_DEC1 / 8; }
    reinterpret_cast<uint4*>(Wf)[i] = cvt8(src + (size_t)(i - base) * 8);
}

// ---- generic single-tensor convert (x0) ----
__global__ __launch_bounds__(256)
void cvt_h_kernel(const float* __restrict__ W, __half* __restrict__ Wf, int n8) {
    int i = blockIdx.x * 256 + threadIdx.x;
    if (i >= n8) return;
    reinterpret_cast<uint4*>(Wf)[i] = cvt8(W + (size_t)i * 8);
}

// ===================== small GEMM (MNet, fp32 SIMT) ========================
__global__ __launch_bounds__(256)
void gemm_bias_kernel(const float* __restrict__ X, const float* __restrict__ W,
                      const float* __restrict__ bias, float* __restrict__ C,
                      int K, int N) {
    const int BM = 64, BN = 64, BK = 16, TM = 4, TN = 4;
    __shared__ __align__(16) float As[BK][BM];
    __shared__ __align__(16) float Bs[BK][BN];
    int tid  = threadIdx.x;
    int n0   = blockIdx.x * BN;
    int m0   = blockIdx.y * BM;
    int tn   = tid & 15, tm = tid >> 4;
    int row0 = tm * TM, col0 = tn * TN;
    int lr   = tid >> 2, ls = tid & 3;
    float acc[TM][TN] = {};
    for (int k0 = 0; k0 < K; k0 += BK) {
        float4 av = *reinterpret_cast<const float4*>(&X[(size_t)(m0 + lr) * K + k0 + ls * 4]);
        As[ls*4+0][lr] = av.x; As[ls*4+1][lr] = av.y; As[ls*4+2][lr] = av.z; As[ls*4+3][lr] = av.w;
        float4 bv = *reinterpret_cast<const float4*>(&W[(size_t)(n0 + lr) * K + k0 + ls * 4]);
        Bs[ls*4+0][lr] = bv.x; Bs[ls*4+1][lr] = bv.y; Bs[ls*4+2][lr] = bv.z; Bs[ls*4+3][lr] = bv.w;
        __syncthreads();
        #pragma unroll
        for (int kk = 0; kk < BK; ++kk) {
            float a[TM], b[TN];
            float4 va = *reinterpret_cast<const float4*>(&As[kk][row0]);
            a[0]=va.x; a[1]=va.y; a[2]=va.z; a[3]=va.w;
            float4 vb = *reinterpret_cast<const float4*>(&Bs[kk][col0]);
            b[0]=vb.x; b[1]=vb.y; b[2]=vb.z; b[3]=vb.w;
            #pragma unroll
            for (int i = 0; i < TM; i++)
                #pragma unroll
                for (int j = 0; j < TN; j++)
                    acc[i][j] = fmaf(a[i], b[j], acc[i][j]);
        }
        __syncthreads();
    }
    #pragma unroll
    for (int i = 0; i < TM; i++)
        #pragma unroll
        for (int j = 0; j < TN; j++)
            C[(size_t)(m0 + row0 + i) * N + n0 + col0 + j] = acc[i][j] + bias[n0 + col0 + j];
}

// ============ BN + PReLU in place (MNet path, fp32 out) ====================
__global__ __launch_bounds__(256)
void bn_prelu_kernel(float* __restrict__ X, const float* __restrict__ g,
                     const float* __restrict__ be, const float* __restrict__ aP,
                     int C) {
    __shared__ float s1[256], s2[256];
    int tid = threadIdx.x;
    int col = blockIdx.x * 2 + (tid & 1);
    int r0  = tid >> 1;
    float sum = 0.f, sq = 0.f;
    for (int r = r0; r < BATCH; r += 128) {
        float v = X[(size_t)r * C + col];
        sum += v; sq += v * v;
    }
    s1[tid] = sum; s2[tid] = sq;
    __syncthreads();
    #pragma unroll
    for (int off = 128; off >= 2; off >>= 1) {
        if (tid < off) { s1[tid] += s1[tid + off]; s2[tid] += s2[tid + off]; }
        __syncthreads();
    }
    float mean = s1[tid & 1] * (1.f / BATCH);
    float var  = s2[tid & 1] * (1.f / BATCH) - mean * mean;
    float sc   = g[col] * rsqrtf(var + EPSV);
    float sh   = be[col] - mean * sc;
    float a    = aP[0];
    for (int r = r0; r < BATCH; r += 128) {
        float v = X[(size_t)r * C + col] * sc + sh;
        X[(size_t)r * C + col] = (v >= 0.f) ? v : a * v;
    }
}

// ====== BN + PReLU fused with fp16 convert (expert path) ===================
__global__ __launch_bounds__(256)
void bn_prelu_h_kernel(const float* __restrict__ X, const float* __restrict__ g,
                       const float* __restrict__ be, const float* __restrict__ aP,
                       int C, __half* __restrict__ Zf) {
    __shared__ float s1[256], s2[256];
    int tid = threadIdx.x;
    int col = blockIdx.x * 2 + (tid & 1);
    int r0  = tid >> 1;
    float sum = 0.f, sq = 0.f;
    for (int r = r0; r < BATCH; r += 128) {
        float v = X[(size_t)r * C + col];
        sum += v; sq += v * v;
    }
    s1[tid] = sum; s2[tid] = sq;
    __syncthreads();
    #pragma unroll
    for (int off = 128; off >= 2; off >>= 1) {
        if (tid < off) { s1[tid] += s1[tid + off]; s2[tid] += s2[tid + off]; }
        __syncthreads();
    }
    float mean = s1[tid & 1] * (1.f / BATCH);
    float var  = s2[tid & 1] * (1.f / BATCH) - mean * mean;
    float sc   = g[col] * rsqrtf(var + EPSV);
    float sh   = be[col] - mean * sc;
    float a    = aP[0];
    for (int r = r0; r < BATCH; r += 128) {
        float v = X[(size_t)r * C + col] * sc + sh;
        v = (v >= 0.f) ? v : a * v;
        Zf[(size_t)r * C + col] = __float2half_rn(v);
    }
}

// =========== single-block global sum (writes g_sum directly) ===============
__global__ __launch_bounds__(1024)
void reduce_w_kernel(const float* __restrict__ w) {
    __shared__ float s[1024];
    int tid = threadIdx.x;
    float a = 0.f;
    const float4* w4 = reinterpret_cast<const float4*>(w);
    for (int i = tid; i < BATCH * NE / 4; i += 1024) {
        float4 v = w4[i];
        a += (v.x + v.y) + (v.z + v.w);
    }
    s[tid] = a; __syncthreads();
    #pragma unroll
    for (int off = 512; off; off >>= 1) {
        if (tid < off) s[tid] += s[tid + off];
        __syncthreads();
    }
    if (tid == 0) g_sum = s[0];
}

// ===================== mma.sync expert GEMM (fp16 single-product) ==========
// accO[b,o] = sum_e (w[b,e]*inv) * (z[b,:] . W[e,o,:] + bias[e,o])
// 3-stage cp.async ring, ONE __syncthreads per chunk; bias folded into accE
// init; out must be zero-initialized (memset); split-K over experts.
template<int IDIM>
__global__ __launch_bounds__(256, 2)
void expert_mma_kernel(const __half* __restrict__ Zf,
                       const __half* __restrict__ Wf,
                       const float* __restrict__ w,
                       const float* __restrict__ bias,
                       float* __restrict__ out,
                       int O, int eper) {
    constexpr int RS    = 80;                 // padded row stride (bytes)
    constexpr int Ao    = 0;
    constexpr int Bo    = 128 * RS;           // 10240
    constexpr int STAGE = Bo + 64 * RS;       // 15360
    constexpr int CPE   = IDIM / 32;          // chunks per expert

    extern __shared__ char smem[];
    uint32_t sb = smem_u32(smem);

    int tid  = threadIdx.x;
    int lane = tid & 31, wid = tid >> 5;
    int wy = wid >> 1, wx = wid & 1;          // 4 M-warps x 2 N-warps
    int m0 = blockIdx.y * 128;
    int n0 = blockIdx.x * 64;
    int e0 = blockIdx.z * eper;
    float inv = 1.f / g_sum;
    const int nc = eper * CPE;

    auto load_chunk = [&](int c, int buf) {
        int e  = e0 + c / CPE;
        int i0 = (c % CPE) * 32;
        uint32_t stg = sb + buf * STAGE;
        // A: Zf tile 128 rows x 32 fp16 = 512 x 16B
        #pragma unroll
        for (int it = 0; it < 2; ++it) {
            int idx = tid + it * 256;
            int row = idx >> 2, ch = idx & 3;
            const __half* src = Zf + (size_t)(m0 + row) * IDIM + i0 + ch * 8;
            CP_ASYNC16(stg + Ao + row * RS + ch * 16, src);
        }
        // B: Wf tile 64 rows x 32 fp16 = 256 x 16B
        {
            int row = tid >> 2, ch = tid & 3;
            const __half* src = Wf + ((size_t)e * O + n0 + row) * IDIM + i0 + ch * 8;
            CP_ASYNC16(stg + Bo + row * RS + ch * 16, src);
        }
        CP_COMMIT();
    };

    float accE[2][4][4];
    float accO[2][4][4] = {};
    int g   = lane >> 2;
    int tig = lane & 3;

    // bias init helper: accE <- bias[e, col] (cols depend on nt only)
    auto set_bias = [&](int e) {
        #pragma unroll
        for (int nt = 0; nt < 4; ++nt) {
            int col = n0 + wx*32 + nt*8 + tig*2;
            float2 bv = *reinterpret_cast<const float2*>(&bias[(size_t)e * O + col]);
            #pragma unroll
            for (int mt = 0; mt < 2; ++mt) {
                accE[mt][nt][0] = bv.x; accE[mt][nt][1] = bv.y;
                accE[mt][nt][2] = bv.x; accE[mt][nt][3] = bv.y;
            }
        }
    };
    set_bias(e0);

    // ldmatrix address constants
    int arow  = lane & 15;
    int acolb = (lane >> 4) * 16;
    int nrow  = (lane & 7) + ((lane >> 4) << 3);
    int bcolb = ((lane >> 3) & 1) * 16;

    // prologue: fill 2 of 3 stages
    load_chunk(0, 0);
    load_chunk(1, 1);

    int buf = 0;
    for (int c = 0; c < nc; ++c) {
        if (c + 1 < nc) CP_WAIT1(); else CP_WAIT0();
        __syncthreads();                      // single barrier per chunk

        uint32_t stg = sb + buf * STAGE;
        #pragma unroll
        for (int kk = 0; kk < 2; ++kk) {
            uint32_t a_f[2][4];
            #pragma unroll
            for (int mt = 0; mt < 2; ++mt) {
                uint32_t ra = stg + Ao + (wy*32 + mt*16 + arow) * RS + kk*32 + acolb;
                LDSM4(a_f[mt], ra);
            }
            uint32_t b_f[2][4];
            #pragma unroll
            for (int p = 0; p < 2; ++p) {
                uint32_t rb = stg + Bo + (wx*32 + p*16 + nrow) * RS + kk*32 + bcolb;
                LDSM4(b_f[p], rb);
            }
            #pragma unroll
            for (int mt = 0; mt < 2; ++mt)
                #pragma unroll
                for (int p = 0; p < 2; ++p)
                    #pragma unroll
                    for (int h = 0; h < 2; ++h)
                        MMA16816H(accE[mt][p*2 + h], a_f[mt],
                                  b_f[p][h*2], b_f[p][h*2+1]);
        }

        // issue loads for chunk c+2 into the stage retired at chunk c-1
        if (c + 2 < nc) {
            int nb = buf + 2; if (nb >= 3) nb -= 3;
            load_chunk(c + 2, nb);
        }

        // expert boundary: fold w[b,e]*inv into output accumulator
        if (((c + 1) & (CPE - 1)) == 0) {
            int e = e0 + c / CPE;
            float wv0[2], wv1[2];
            #pragma unroll
            for (int mt = 0; mt < 2; ++mt) {
                int r = m0 + wy*32 + mt*16 + g;
                wv0[mt] = w[(size_t)r * NE + e] * inv;
                wv1[mt] = w[(size_t)(r + 8) * NE + e] * inv;
            }
            #pragma unroll
            for (int mt = 0; mt < 2; ++mt)
                #pragma unroll
                for (int nt = 0; nt < 4; ++nt) {
                    accO[mt][nt][0] = fmaf(wv0[mt], accE[mt][nt][0], accO[mt][nt][0]);
                    accO[mt][nt][1] = fmaf(wv0[mt], accE[mt][nt][1], accO[mt][nt][1]);
                    accO[mt][nt][2] = fmaf(wv1[mt], accE[mt][nt][2], accO[mt][nt][2]);
                    accO[mt][nt][3] = fmaf(wv1[mt], accE[mt][nt][3], accO[mt][nt][3]);
                }
            if (c + 1 < nc) set_bias(e + 1);
        }

        if (++buf >= 3) buf -= 3;
    }

    // ---- epilogue: atomicAdd into zero-initialized out ----
    #pragma unroll
    for (int mt = 0; mt < 2; ++mt)
        #pragma unroll
        for (int nt = 0; nt < 4; ++nt) {
            int row = m0 + wy*32 + mt*16 + g;
            int col = n0 + wx*32 + nt*8 + tig*2;
            float* p0 = out + (size_t)row * O + col;
            atomicAdd(p0,     accO[mt][nt][0]);
            atomicAdd(p0 + 1, accO[mt][nt][1]);
            float* p1 = p0 + (size_t)8 * O;
            atomicAdd(p1,     accO[mt][nt][2]);
            atomicAdd(p1 + 1, accO[mt][nt][3]);
        }
}

// ===========================================================================
extern "C" void kernel_launch(void* const* d_in, const int* in_sizes, int n_in,
                              void* d_out, int out_size) {
    const float* m0    = (const float*)d_in[0];
    const float* x0    = (const float*)d_in[1];
    const float* mW1   = (const float*)d_in[2];
    const float* mb1   = (const float*)d_in[3];
    const float* mg1   = (const float*)d_in[4];
    const float* mbe1  = (const float*)d_in[5];
    const float* ma1   = (const float*)d_in[6];
    const float* mW2   = (const float*)d_in[7];
    const float* mb2   = (const float*)d_in[8];
    const float* mg2   = (const float*)d_in[9];
    const float* mbe2  = (const float*)d_in[10];
    const float* ma2   = (const float*)d_in[11];
    const float* mW3   = (const float*)d_in[12];
    const float* mb3   = (const float*)d_in[13];
    const float* mg3   = (const float*)d_in[14];
    const float* mbe3  = (const float*)d_in[15];
    const float* ma3   = (const float*)d_in[16];
    const float* Wenc0 = (const float*)d_in[17];
    const float* benc0 = (const float*)d_in[18];
    const float* Wenc1 = (const float*)d_in[19];
    const float* benc1 = (const float*)d_in[20];
    const float* Wdec0 = (const float*)d_in[21];
    const float* bdec0 = (const float*)d_in[22];
    const float* Wdec1 = (const float*)d_in[23];
    const float* bdec1 = (const float*)d_in[24];
    const float* bng   = (const float*)d_in[25];
    const float* bnb   = (const float*)d_in[26];
    const float* aP    = (const float*)d_in[27];
    float* out = (float*)d_out;

    float *b0, *b1, *b2, *wb;
    __half *Wf, *Zf;
    cudaGetSymbolAddress((void**)&b0, g_buf0);
    cudaGetSymbolAddress((void**)&b1, g_buf1);
    cudaGetSymbolAddress((void**)&b2, g_buf2);
    cudaGetSymbolAddress((void**)&wb, g_w);
    cudaGetSymbolAddress((void**)&Wf, g_Wf);
    cudaGetSymbolAddress((void**)&Zf, g_Zf);

    const int SMEM = 46080;   // 3 stages x 15360
    cudaFuncSetAttribute(expert_mma_kernel<64>,
                         cudaFuncAttributeMaxDynamicSharedMemorySize, SMEM);
    cudaFuncSetAttribute(expert_mma_kernel<256>,
                         cudaFuncAttributeMaxDynamicSharedMemorySize, SMEM);

    // ---- convert all expert weights to fp16 (one kernel) ----
    cvt_all_kernel<<<W_TOTAL / 8 / 256, 256>>>(Wenc0, Wenc1, Wdec0, Wdec1, Wf);

    // ---- MNet: 3x (Linear -> BN -> PReLU) -> w [4096,64] ----
    gemm_bias_kernel<<<dim3(4, 64), 256>>>(m0, mW1, mb1, b0, 128, 256);
    bn_prelu_kernel<<<128, 256>>>(b0, mg1, mbe1, ma1, 256);
    gemm_bias_kernel<<<dim3(2, 64), 256>>>(b0, mW2, mb2, b1, 256, 128);
    bn_prelu_kernel<<<64, 256>>>(b1, mg2, mbe2, ma2, 128);
    gemm_bias_kernel<<<dim3(1, 64), 256>>>(b1, mW3, mb3, wb, 128, 64);
    bn_prelu_kernel<<<32, 256>>>(wb, mg3, mbe3, ma3, 64);
    reduce_w_kernel<<<1, 1024>>>(wb);

    // ---- encoder layer 0: x0[4096,64] -> b2[4096,256] ----
    cvt_h_kernel<<<128, 256>>>(x0, Zf, BATCH * 64 / 8);
    cudaMemsetAsync(b2, 0, BATCH * 256 * sizeof(float));
    expert_mma_kernel<64><<<dim3(4, 32, 2), 256, SMEM>>>(
        Zf, Wf + OFF_ENC0, wb, benc0, b2, 256, 32);
    bn_prelu_h_kernel<<<128, 256>>>(b2, bng, bnb, aP, 256, Zf);

    // ---- encoder layer 1: -> b0 ----
    cudaMemsetAsync(b0, 0, BATCH * 256 * sizeof(float));
    expert_mma_kernel<256><<<dim3(4, 32, 4), 256, SMEM>>>(
        Zf, Wf + OFF_ENC1, wb, benc1, b0, 256, 16);
    bn_prelu_h_kernel<<<128, 256>>>(b0, bng, bnb, aP, 256, Zf);

    // ---- decoder layer 0: -> b1 ----
    cudaMemsetAsync(b1, 0, BATCH * 256 * sizeof(float));
    expert_mma_kernel<256><<<dim3(4, 32, 4), 256, SMEM>>>(
        Zf, Wf + OFF_DEC0, wb, bdec0, b1, 256, 16);
    bn_prelu_h_kernel<<<128, 256>>>(b1, bng, bnb, aP, 256, Zf);

    // ---- decoder layer 1 (no BN/PReLU): -> out [4096,64] ----
    cudaMemsetAsync(out, 0, BATCH * 64 * sizeof(float));
    expert_mma_kernel<256><<<dim3(1, 32, 8), 256, SMEM>>>(
        Zf, Wf + OFF_DEC1, wb, bdec1, out, 64, 8);
}

// round 9
// speedup vs baseline: 4.8554x; 1.0143x over previous
#include <cuda_runtime.h>
#include <cuda_fp16.h>
#include <cstdint>

#define BATCH 4096
#define NE    64
#define EPSV  1e-5f

// ===================== device scratch (no runtime alloc) ====================
__device__ __align__(16) float g_buf0[BATCH * 256];
__device__ __align__(16) float g_buf1[BATCH * 256];
__device__ __align__(16) float g_buf2[BATCH * 256];
__device__ __align__(16) float g_w   [BATCH * NE];
__device__ float g_sum;

// activation fp16 (max 4096 x 256)
__device__ __align__(16) __half g_Zf[BATCH * 256];

// fp16 weights: enc0(1M) enc1(4M) dec0(4M) dec1(1M) = 10.5M elems
#define OFF_ENC0 0
#define OFF_ENC1 1048576
#define OFF_DEC0 5242880
#define OFF_DEC1 9437184
#define W_TOTAL  10485760
__device__ __align__(16) __half g_Wf[W_TOTAL];

// ===================== PTX helpers (base sm_103 target only) ===============
__device__ __forceinline__ uint32_t smem_u32(const void* p) {
    uint32_t a;
    asm("{ .reg .u64 t; cvta.to.shared.u64 t, %1; cvt.u32.u64 %0, t; }"
        : "=r"(a) : "l"(p));
    return a;
}

#define LDSM4(r, a) \
    asm volatile("ldmatrix.sync.aligned.m8n8.x4.shared.b16 {%0,%1,%2,%3}, [%4];" \
        : "=r"((r)[0]), "=r"((r)[1]), "=r"((r)[2]), "=r"((r)[3]) : "r"(a))

#define MMA16816H(d, a, b0v, b1v) \
    asm volatile("mma.sync.aligned.m16n8k16.row.col.f32.f16.f16.f32 " \
        "{%0,%1,%2,%3}, {%4,%5,%6,%7}, {%8,%9}, {%0,%1,%2,%3};" \
        : "+f"((d)[0]), "+f"((d)[1]), "+f"((d)[2]), "+f"((d)[3]) \
        : "r"((a)[0]), "r"((a)[1]), "r"((a)[2]), "r"((a)[3]), "r"(b0v), "r"(b1v))

#define CP_ASYNC16(dst, src) \
    asm volatile("cp.async.cg.shared.global [%0], [%1], 16;" :: "r"(dst), "l"(src))
#define CP_COMMIT() asm volatile("cp.async.commit_group;" ::: "memory")
#define CP_WAIT2()  asm volatile("cp.async.wait_group 2;" ::: "memory")
#define CP_WAIT1()  asm volatile("cp.async.wait_group 1;" ::: "memory")
#define CP_WAIT0()  asm volatile("cp.async.wait_group 0;" ::: "memory")

// ============ convert fp32 -> fp16 (8 elems per thread) ====================
__device__ __forceinline__ uint4 cvt8(const float* __restrict__ src8) {
    float4 v0 = reinterpret_cast<const float4*>(src8)[0];
    float4 v1 = reinterpret_cast<const float4*>(src8)[1];
    __half2 h0 = __floats2half2_rn(v0.x, v0.y);
    __half2 h1 = __floats2half2_rn(v0.z, v0.w);
    __half2 h2 = __floats2half2_rn(v1.x, v1.y);
    __half2 h3 = __floats2half2_rn(v1.z, v1.w);
    return make_uint4(*reinterpret_cast<uint32_t*>(&h0),
                      *reinterpret_cast<uint32_t*>(&h1),
                      *reinterpret_cast<uint32_t*>(&h2),
                      *reinterpret_cast<uint32_t*>(&h3));
}

__global__ __launch_bounds__(256)
void cvt_all_kernel(const float* __restrict__ W0, const float* __restrict__ W1,
                    const float* __restrict__ W2, const float* __restrict__ W3,
                    __half* __restrict__ Wf) {
    int i = blockIdx.x * 256 + threadIdx.x;    // i over W_TOTAL/8
    const float* src; int base;
    if      (i < OFF_ENC1 / 8) { src = W0; base = 0; }
    else if (i < OFF_DEC0 / 8) { src = W1; base = OFF_ENC1 / 8; }
    else if (i < OFF_DEC1 / 8) { src = W2; base = OFF_DEC0 / 8; }
    else                       { src = W3; base = OFF_DEC1 / 8; }
    reinterpret_cast<uint4*>(Wf)[i] = cvt8(src + (size_t)(i - base) * 8);
}

__global__ __launch_bounds__(256)
void cvt_h_kernel(const float* __restrict__ W, __half* __restrict__ Wf, int n8) {
    int i = blockIdx.x * 256 + threadIdx.x;
    if (i >= n8) return;
    reinterpret_cast<uint4*>(Wf)[i] = cvt8(W + (size_t)i * 8);
}

// ===================== small GEMM (MNet, fp32 SIMT) ========================
__global__ __launch_bounds__(256)
void gemm_bias_kernel(const float* __restrict__ X, const float* __restrict__ W,
                      const float* __restrict__ bias, float* __restrict__ C,
                      int K, int N) {
    const int BM = 64, BN = 64, BK = 16, TM = 4, TN = 4;
    __shared__ __align__(16) float As[BK][BM];
    __shared__ __align__(16) float Bs[BK][BN];
    int tid  = threadIdx.x;
    int n0   = blockIdx.x * BN;
    int m0   = blockIdx.y * BM;
    int tn   = tid & 15, tm = tid >> 4;
    int row0 = tm * TM, col0 = tn * TN;
    int lr   = tid >> 2, ls = tid & 3;
    float acc[TM][TN] = {};
    for (int k0 = 0; k0 < K; k0 += BK) {
        float4 av = *reinterpret_cast<const float4*>(&X[(size_t)(m0 + lr) * K + k0 + ls * 4]);
        As[ls*4+0][lr] = av.x; As[ls*4+1][lr] = av.y; As[ls*4+2][lr] = av.z; As[ls*4+3][lr] = av.w;
        float4 bv = *reinterpret_cast<const float4*>(&W[(size_t)(n0 + lr) * K + k0 + ls * 4]);
        Bs[ls*4+0][lr] = bv.x; Bs[ls*4+1][lr] = bv.y; Bs[ls*4+2][lr] = bv.z; Bs[ls*4+3][lr] = bv.w;
        __syncthreads();
        #pragma unroll
        for (int kk = 0; kk < BK; ++kk) {
            float a[TM], b[TN];
            float4 va = *reinterpret_cast<const float4*>(&As[kk][row0]);
            a[0]=va.x; a[1]=va.y; a[2]=va.z; a[3]=va.w;
            float4 vb = *reinterpret_cast<const float4*>(&Bs[kk][col0]);
            b[0]=vb.x; b[1]=vb.y; b[2]=vb.z; b[3]=vb.w;
            #pragma unroll
            for (int i = 0; i < TM; i++)
                #pragma unroll
                for (int j = 0; j < TN; j++)
                    acc[i][j] = fmaf(a[i], b[j], acc[i][j]);
        }
        __syncthreads();
    }
    #pragma unroll
    for (int i = 0; i < TM; i++)
        #pragma unroll
        for (int j = 0; j < TN; j++)
            C[(size_t)(m0 + row0 + i) * N + n0 + col0 + j] = acc[i][j] + bias[n0 + col0 + j];
}

// ============ BN + PReLU in place (MNet path, fp32 out) ====================
__global__ __launch_bounds__(256)
void bn_prelu_kernel(float* __restrict__ X, const float* __restrict__ g,
                     const float* __restrict__ be, const float* __restrict__ aP,
                     int C) {
    __shared__ float s1[256], s2[256];
    int tid = threadIdx.x;
    int col = blockIdx.x * 2 + (tid & 1);
    int r0  = tid >> 1;
    float sum = 0.f, sq = 0.f;
    for (int r = r0; r < BATCH; r += 128) {
        float v = X[(size_t)r * C + col];
        sum += v; sq += v * v;
    }
    s1[tid] = sum; s2[tid] = sq;
    __syncthreads();
    #pragma unroll
    for (int off = 128; off >= 2; off >>= 1) {
        if (tid < off) { s1[tid] += s1[tid + off]; s2[tid] += s2[tid + off]; }
        __syncthreads();
    }
    float mean = s1[tid & 1] * (1.f / BATCH);
    float var  = s2[tid & 1] * (1.f / BATCH) - mean * mean;
    float sc   = g[col] * rsqrtf(var + EPSV);
    float sh   = be[col] - mean * sc;
    float a    = aP[0];
    for (int r = r0; r < BATCH; r += 128) {
        float v = X[(size_t)r * C + col] * sc + sh;
        X[(size_t)r * C + col] = (v >= 0.f) ? v : a * v;
    }
}

// ====== BN + PReLU fused with fp16 convert (expert path) ===================
__global__ __launch_bounds__(256)
void bn_prelu_h_kernel(const float* __restrict__ X, const float* __restrict__ g,
                       const float* __restrict__ be, const float* __restrict__ aP,
                       int C, __half* __restrict__ Zf) {
    __shared__ float s1[256], s2[256];
    int tid = threadIdx.x;
    int col = blockIdx.x * 2 + (tid & 1);
    int r0  = tid >> 1;
    float sum = 0.f, sq = 0.f;
    for (int r = r0; r < BATCH; r += 128) {
        float v = X[(size_t)r * C + col];
        sum += v; sq += v * v;
    }
    s1[tid] = sum; s2[tid] = sq;
    __syncthreads();
    #pragma unroll
    for (int off = 128; off >= 2; off >>= 1) {
        if (tid < off) { s1[tid] += s1[tid + off]; s2[tid] += s2[tid + off]; }
        __syncthreads();
    }
    float mean = s1[tid & 1] * (1.f / BATCH);
    float var  = s2[tid & 1] * (1.f / BATCH) - mean * mean;
    float sc   = g[col] * rsqrtf(var + EPSV);
    float sh   = be[col] - mean * sc;
    float a    = aP[0];
    for (int r = r0; r < BATCH; r += 128) {
        float v = X[(size_t)r * C + col] * sc + sh;
        v = (v >= 0.f) ? v : a * v;
        Zf[(size_t)r * C + col] = __float2half_rn(v);
    }
}

// =========== single-block global sum (writes g_sum directly) ===============
__global__ __launch_bounds__(1024)
void reduce_w_kernel(const float* __restrict__ w) {
    __shared__ float s[1024];
    int tid = threadIdx.x;
    float a = 0.f;
    const float4* w4 = reinterpret_cast<const float4*>(w);
    for (int i = tid; i < BATCH * NE / 4; i += 1024) {
        float4 v = w4[i];
        a += (v.x + v.y) + (v.z + v.w);
    }
    s[tid] = a; __syncthreads();
    #pragma unroll
    for (int off = 512; off; off >>= 1) {
        if (tid < off) s[tid] += s[tid + off];
        __syncthreads();
    }
    if (tid == 0) g_sum = s[0];
}

// ===================== mma.sync expert GEMM (fp16) =========================
// accO[b,o] = sum_e (w[b,e]/sum) * (z[b,:] . W[e,o,:] + bias[e,o])
// BM=128, BN templated (128 or 64); 8 warps as 4M x 2N, warp tile 32 x BN/2.
// 4-stage cp.async ring, one __syncthreads per chunk; bias folded into accE;
// out must be zero-initialized; split-K over experts + atomicAdd.
template<int IDIM, int BN, int NCTA>
__global__ __launch_bounds__(256, NCTA)
void expert_mma_kernel(const __half* __restrict__ Zf,
                       const __half* __restrict__ Wf,
                       const float* __restrict__ w,
                       const float* __restrict__ bias,
                       float* __restrict__ out,
                       int O, int eper) {
    constexpr int RS    = 80;                 // padded row stride (bytes)
    constexpr int Ao    = 0;
    constexpr int Bo    = 128 * RS;           // A region: 128 rows
    constexpr int STAGE = (128 + BN) * RS;
    constexpr int CPE   = IDIM / 32;          // chunks per expert
    constexpr int P     = BN / 32;            // 16-col LDSM groups per warp
    constexpr int NT    = BN / 16;            // n8-tiles per warp

    extern __shared__ char smem[];
    uint32_t sb = smem_u32(smem);

    int tid  = threadIdx.x;
    int lane = tid & 31, wid = tid >> 5;
    int wy = wid >> 1, wx = wid & 1;          // 4 M-warps x 2 N-warps
    int m0 = blockIdx.y * 128;
    int n0 = blockIdx.x * BN;
    int e0 = blockIdx.z * eper;
    float inv = 1.f / g_sum;
    const int nc = eper * CPE;

    auto load_chunk = [&](int c, int buf) {
        int e  = e0 + c / CPE;
        int i0 = (c % CPE) * 32;
        uint32_t stg = sb + buf * STAGE;
        // A: 128 rows x 32 fp16 = 512 x 16B
        #pragma unroll
        for (int it = 0; it < 2; ++it) {
            int idx = tid + it * 256;
            int row = idx >> 2, ch = idx & 3;
            const __half* src = Zf + (size_t)(m0 + row) * IDIM + i0 + ch * 8;
            CP_ASYNC16(stg + Ao + row * RS + ch * 16, src);
        }
        // B: BN rows x 32 fp16 = BN*4 x 16B
        #pragma unroll
        for (int it = 0; it < BN / 64; ++it) {
            int idx = tid + it * 256;
            int row = idx >> 2, ch = idx & 3;
            const __half* src = Wf + ((size_t)e * O + n0 + row) * IDIM + i0 + ch * 8;
            CP_ASYNC16(stg + Bo + row * RS + ch * 16, src);
        }
        CP_COMMIT();
    };

    float accE[2][NT][4];
    float accO[2][NT][4] = {};
    int g   = lane >> 2;
    int tig = lane & 3;

    auto set_bias = [&](int e) {
        #pragma unroll
        for (int nt = 0; nt < NT; ++nt) {
            int col = n0 + wx * (BN / 2) + nt * 8 + tig * 2;
            float2 bv = *reinterpret_cast<const float2*>(&bias[(size_t)e * O + col]);
            #pragma unroll
            for (int mt = 0; mt < 2; ++mt) {
                accE[mt][nt][0] = bv.x; accE[mt][nt][1] = bv.y;
                accE[mt][nt][2] = bv.x; accE[mt][nt][3] = bv.y;
            }
        }
    };
    set_bias(e0);

    // ldmatrix address constants
    int arow  = lane & 15;
    int acolb = (lane >> 4) * 16;
    int nrow  = (lane & 7) + ((lane >> 4) << 3);
    int bcolb = ((lane >> 3) & 1) * 16;

    // prologue: fill 3 of 4 stages
    load_chunk(0, 0);
    if (nc > 1) load_chunk(1, 1);
    if (nc > 2) load_chunk(2, 2);

    int buf = 0;
    for (int c = 0; c < nc; ++c) {
        if      (c + 2 < nc) CP_WAIT2();
        else if (c + 1 < nc) CP_WAIT1();
        else                 CP_WAIT0();
        __syncthreads();                      // single barrier per chunk

        uint32_t stg = sb + buf * STAGE;
        #pragma unroll
        for (int kk = 0; kk < 2; ++kk) {
            uint32_t a_f[2][4];
            #pragma unroll
            for (int mt = 0; mt < 2; ++mt) {
                uint32_t ra = stg + Ao + (wy*32 + mt*16 + arow) * RS + kk*32 + acolb;
                LDSM4(a_f[mt], ra);
            }
            uint32_t b_f[P][4];
            #pragma unroll
            for (int p = 0; p < P; ++p) {
                uint32_t rb = stg + Bo + (wx*(BN/2) + p*16 + nrow) * RS + kk*32 + bcolb;
                LDSM4(b_f[p], rb);
            }
            #pragma unroll
            for (int mt = 0; mt < 2; ++mt)
                #pragma unroll
                for (int p = 0; p < P; ++p)
                    #pragma unroll
                    for (int h = 0; h < 2; ++h)
                        MMA16816H(accE[mt][p*2 + h], a_f[mt],
                                  b_f[p][h*2], b_f[p][h*2+1]);
        }

        // issue loads for chunk c+3 into the stage retired at chunk c-1
        if (c + 3 < nc) {
            int nb = buf + 3; if (nb >= 4) nb -= 4;
            load_chunk(c + 3, nb);
        }

        // expert boundary: fold w[b,e]*inv into output accumulator
        if (((c + 1) & (CPE - 1)) == 0) {
            int e = e0 + c / CPE;
            float wv0[2], wv1[2];
            #pragma unroll
            for (int mt = 0; mt < 2; ++mt) {
                int r = m0 + wy*32 + mt*16 + g;
                wv0[mt] = w[(size_t)r * NE + e] * inv;
                wv1[mt] = w[(size_t)(r + 8) * NE + e] * inv;
            }
            #pragma unroll
            for (int mt = 0; mt < 2; ++mt)
                #pragma unroll
                for (int nt = 0; nt < NT; ++nt) {
                    accO[mt][nt][0] = fmaf(wv0[mt], accE[mt][nt][0], accO[mt][nt][0]);
                    accO[mt][nt][1] = fmaf(wv0[mt], accE[mt][nt][1], accO[mt][nt][1]);
                    accO[mt][nt][2] = fmaf(wv1[mt], accE[mt][nt][2], accO[mt][nt][2]);
                    accO[mt][nt][3] = fmaf(wv1[mt], accE[mt][nt][3], accO[mt][nt][3]);
                }
            if (c + 1 < nc) set_bias(e + 1);
        }

        if (++buf >= 4) buf -= 4;
    }

    // ---- epilogue: atomicAdd into zero-initialized out ----
    #pragma unroll
    for (int mt = 0; mt < 2; ++mt)
        #pragma unroll
        for (int nt = 0; nt < NT; ++nt) {
            int row = m0 + wy*32 + mt*16 + g;
            int col = n0 + wx*(BN/2) + nt*8 + tig*2;
            float* p0 = out + (size_t)row * O + col;
            atomicAdd(p0,     accO[mt][nt][0]);
            atomicAdd(p0 + 1, accO[mt][nt][1]);
            float* p1 = p0 + (size_t)8 * O;
            atomicAdd(p1,     accO[mt][nt][2]);
            atomicAdd(p1 + 1, accO[mt][nt][3]);
        }
}

// ===========================================================================
extern "C" void kernel_launch(void* const* d_in, const int* in_sizes, int n_in,
                              void* d_out, int out_size) {
    const float* m0    = (const float*)d_in[0];
    const float* x0    = (const float*)d_in[1];
    const float* mW1   = (const float*)d_in[2];
    const float* mb1   = (const float*)d_in[3];
    const float* mg1   = (const float*)d_in[4];
    const float* mbe1  = (const float*)d_in[5];
    const float* ma1   = (const float*)d_in[6];
    const float* mW2   = (const float*)d_in[7];
    const float* mb2   = (const float*)d_in[8];
    const float* mg2   = (const float*)d_in[9];
    const float* mbe2  = (const float*)d_in[10];
    const float* ma2   = (const float*)d_in[11];
    const float* mW3   = (const float*)d_in[12];
    const float* mb3   = (const float*)d_in[13];
    const float* mg3   = (const float*)d_in[14];
    const float* mbe3  = (const float*)d_in[15];
    const float* ma3   = (const float*)d_in[16];
    const float* Wenc0 = (const float*)d_in[17];
    const float* benc0 = (const float*)d_in[18];
    const float* Wenc1 = (const float*)d_in[19];
    const float* benc1 = (const float*)d_in[20];
    const float* Wdec0 = (const float*)d_in[21];
    const float* bdec0 = (const float*)d_in[22];
    const float* Wdec1 = (const float*)d_in[23];
    const float* bdec1 = (const float*)d_in[24];
    const float* bng   = (const float*)d_in[25];
    const float* bnb   = (const float*)d_in[26];
    const float* aP    = (const float*)d_in[27];
    float* out = (float*)d_out;

    float *b0, *b1, *b2, *wb;
    __half *Wf, *Zf;
    cudaGetSymbolAddress((void**)&b0, g_buf0);
    cudaGetSymbolAddress((void**)&b1, g_buf1);
    cudaGetSymbolAddress((void**)&b2, g_buf2);
    cudaGetSymbolAddress((void**)&wb, g_w);
    cudaGetSymbolAddress((void**)&Wf, g_Wf);
    cudaGetSymbolAddress((void**)&Zf, g_Zf);

    const int SMEM128 = 4 * (128 + 128) * 80;   // 81920
    const int SMEM64  = 4 * (128 +  64) * 80;   // 61440
    cudaFuncSetAttribute(expert_mma_kernel<64, 128, 1>,
                         cudaFuncAttributeMaxDynamicSharedMemorySize, SMEM128);
    cudaFuncSetAttribute(expert_mma_kernel<256, 128, 1>,
                         cudaFuncAttributeMaxDynamicSharedMemorySize, SMEM128);
    cudaFuncSetAttribute(expert_mma_kernel<256, 64, 2>,
                         cudaFuncAttributeMaxDynamicSharedMemorySize, SMEM64);

    // ---- convert all expert weights to fp16 (one kernel) ----
    cvt_all_kernel<<<W_TOTAL / 8 / 256, 256>>>(Wenc0, Wenc1, Wdec0, Wdec1, Wf);

    // ---- MNet: 3x (Linear -> BN -> PReLU) -> w [4096,64] ----
    gemm_bias_kernel<<<dim3(4, 64), 256>>>(m0, mW1, mb1, b0, 128, 256);
    bn_prelu_kernel<<<128, 256>>>(b0, mg1, mbe1, ma1, 256);
    gemm_bias_kernel<<<dim3(2, 64), 256>>>(b0, mW2, mb2, b1, 256, 128);
    bn_prelu_kernel<<<64, 256>>>(b1, mg2, mbe2, ma2, 128);
    gemm_bias_kernel<<<dim3(1, 64), 256>>>(b1, mW3, mb3, wb, 128, 64);
    bn_prelu_kernel<<<32, 256>>>(wb, mg3, mbe3, ma3, 64);
    reduce_w_kernel<<<1, 1024>>>(wb);

    // ---- encoder layer 0: x0[4096,64] -> b2[4096,256] ----
    cvt_h_kernel<<<128, 256>>>(x0, Zf, BATCH * 64 / 8);
    cudaMemsetAsync(b2, 0, BATCH * 256 * sizeof(float));
    expert_mma_kernel<64, 128, 1><<<dim3(2, 32, 4), 256, SMEM128>>>(
        Zf, Wf + OFF_ENC0, wb, benc0, b2, 256, 16);
    bn_prelu_h_kernel<<<128, 256>>>(b2, bng, bnb, aP, 256, Zf);

    // ---- encoder layer 1: -> b0 ----
    cudaMemsetAsync(b0, 0, BATCH * 256 * sizeof(float));
    expert_mma_kernel<256, 128, 1><<<dim3(2, 32, 4), 256, SMEM128>>>(
        Zf, Wf + OFF_ENC1, wb, benc1, b0, 256, 16);
    bn_prelu_h_kernel<<<128, 256>>>(b0, bng, bnb, aP, 256, Zf);

    // ---- decoder layer 0: -> b1 ----
    cudaMemsetAsync(b1, 0, BATCH * 256 * sizeof(float));
    expert_mma_kernel<256, 128, 1><<<dim3(2, 32, 4), 256, SMEM128>>>(
        Zf, Wf + OFF_DEC0, wb, bdec0, b1, 256, 16);
    bn_prelu_h_kernel<<<128, 256>>>(b1, bng, bnb, aP, 256, Zf);

    // ---- decoder layer 1 (no BN/PReLU): -> out [4096,64] ----
    cudaMemsetAsync(out, 0, BATCH * 64 * sizeof(float));
    expert_mma_kernel<256, 64, 2><<<dim3(1, 32, 8), 256, SMEM64>>>(
        Zf, Wf + OFF_DEC1, wb, bdec1, out, 64, 8);
}